// round 5
// baseline (speedup 1.0000x reference)
#include <cuda_runtime.h>

#define N_NODES 100000
#define N_EDGES 1250000
#define IN_DIM  64
#define HID     128
#define OUT_DIM 64

typedef unsigned long long ull;

// ---------------- scratch (static device globals; 16B-aligned) ------------
__device__ float4 g_agg4[(size_t)N_NODES * IN_DIM / 4];   // 25.6 MB
__device__ float  g_deg [N_NODES];
__device__ float4 g_h1_4[(size_t)N_NODES * HID / 4];      // 51.2 MB
__device__ float4 g_h2_4[(size_t)N_NODES * HID / 4];      // 51.2 MB

// ---------------- packed f32x2 helpers ------------------------------------
__device__ __forceinline__ ull pack2(float lo, float hi) {
    ull r;
    asm("mov.b64 %0, {%1, %2};" : "=l"(r) : "f"(lo), "f"(hi));
    return r;
}
__device__ __forceinline__ void ffma2(ull& d, ull a, ull b) {
    asm("fma.rn.f32x2 %0, %1, %2, %0;" : "+l"(d) : "l"(a), "l"(b));
}
__device__ __forceinline__ float2 unpack2(ull v) {
    float2 f;
    asm("mov.b64 {%0, %1}, %2;" : "=f"(f.x), "=f"(f.y) : "l"(v));
    return f;
}

__device__ __forceinline__ void red_add_v4(float* p, float4 v) {
    asm volatile("red.global.add.v4.f32 [%0], {%1, %2, %3, %4};"
                 :: "l"(p), "f"(v.x), "f"(v.y), "f"(v.z), "f"(v.w)
                 : "memory");
}

// ---------------- zero agg + deg ------------------------------------------
__global__ void zero_kernel() {
    int i = blockIdx.x * blockDim.x + threadIdx.x;
    const int n4 = (N_NODES * IN_DIM) / 4;
    if (i < n4) g_agg4[i] = make_float4(0.f, 0.f, 0.f, 0.f);
    if (i < N_NODES) g_deg[i] = 0.f;
}

// ---------------- scatter: agg[row] += x[col]; deg[row] += 1 --------------
__global__ void scatter_kernel(const float* __restrict__ x,
                               const int* __restrict__ ei) {
    long long t = (long long)blockIdx.x * blockDim.x + threadIdx.x;
    int e = (int)(t >> 3);
    if (e >= N_EDGES) return;
    int p = (int)(t & 7);
    int row = ei[e];
    int col = ei[N_EDGES + e];
    const float4* src = reinterpret_cast<const float4*>(x + (size_t)col * IN_DIM) + p * 2;
    float* dst = reinterpret_cast<float*>(g_agg4) + (size_t)row * IN_DIM + p * 8;
    float4 v0 = src[0];
    float4 v1 = src[1];
    red_add_v4(dst, v0);
    red_add_v4(dst + 4, v1);
    if (p == 0) atomicAdd(&g_deg[row], 1.0f);
}

// ---------------- fused-layer SGEMM, packed f32x2 FFMA2 -------------------
// out[M, NOUT] = act(A[M,128] @ W[128,NOUT] + b)
// BM=128 rows/block, 256 threads: tm=tid>>5 -> 16-row slab (8 row-pairs),
// tn=tid&31 -> TN cols. As k-major [K][BM]: A pairs loaded as ld.shared.b64.
// CONCAT layer also folds the deg-mean division into the As fill.
template<int NOUT, bool RELU, bool CONCAT>
__global__ void __launch_bounds__(256, 1)
mlp_kernel(const float* __restrict__ A,
           const float* __restrict__ A2,
           const float* __restrict__ W,
           const float* __restrict__ bias,
           float* __restrict__ out) {
    constexpr int K = 128;
    constexpr int BM = 128;
    constexpr int TN = NOUT / 32;

    extern __shared__ float smem[];
    float* As = smem;              // [K][BM]  (k-major)
    float* Bs = smem + K * BM;     // [K][NOUT]

    int tid = threadIdx.x;
    int m0 = blockIdx.x * BM;

    // --- fill As transposed: i -> (m = i&127, kq = i>>7); m constant/thread
    {
        int m = tid & 127;               // same m for all iterations of this thread
        int node = m0 + m;
        float inv = 1.0f;
        if (CONCAT && node < N_NODES) inv = 1.0f / fmaxf(g_deg[node], 1.0f);
        for (int i = tid; i < BM * (K / 4); i += 256) {
            int kq = i >> 7;             // 0..31
            float4 v = make_float4(0.f, 0.f, 0.f, 0.f);
            if (node < N_NODES) {
                if (CONCAT) {
                    if (kq < 16) {
                        v = reinterpret_cast<const float4*>(A)[(size_t)node * 16 + kq];
                    } else {
                        v = reinterpret_cast<const float4*>(A2)[(size_t)node * 16 + kq - 16];
                        v.x *= inv; v.y *= inv; v.z *= inv; v.w *= inv;
                    }
                } else {
                    v = reinterpret_cast<const float4*>(A)[(size_t)node * 32 + kq];
                }
            }
            int k0 = kq * 4;
            As[(k0 + 0) * BM + m] = v.x;
            As[(k0 + 1) * BM + m] = v.y;
            As[(k0 + 2) * BM + m] = v.z;
            As[(k0 + 3) * BM + m] = v.w;
        }
    }
    // --- fill Bs [K][NOUT] ---
    for (int i = tid; i < K * NOUT / 4; i += 256) {
        reinterpret_cast<float4*>(Bs)[i] = reinterpret_cast<const float4*>(W)[i];
    }
    __syncthreads();

    int tm = tid >> 5;     // 0..7 -> 16-row slab
    int tn = tid & 31;

    ull acc[8][TN];
    #pragma unroll
    for (int r = 0; r < 8; r++)
        #pragma unroll
        for (int j = 0; j < TN; j++) acc[r][j] = 0ull;

    const float* abase = As + tm * 16;

    #pragma unroll 4
    for (int k = 0; k < K; ++k) {
        // A: 8 row-pairs as direct 64-bit shared loads (packed f32x2, no movs)
        const ull* ar = reinterpret_cast<const ull*>(abase + k * BM);
        ull aa[8];
        #pragma unroll
        for (int r = 0; r < 8; r++) aa[r] = ar[r];

        ull bbp[TN];
        if (TN == 4) {
            float4 b4 = reinterpret_cast<const float4*>(Bs + k * NOUT)[tn];
            bbp[0] = pack2(b4.x, b4.x);
            bbp[1] = pack2(b4.y, b4.y);
            bbp[2] = pack2(b4.z, b4.z);
            bbp[3] = pack2(b4.w, b4.w);
        } else {
            float2 b2 = reinterpret_cast<const float2*>(Bs + k * NOUT)[tn];
            bbp[0] = pack2(b2.x, b2.x);
            bbp[1] = pack2(b2.y, b2.y);
        }

        #pragma unroll
        for (int r = 0; r < 8; r++)
            #pragma unroll
            for (int j = 0; j < TN; j++)
                ffma2(acc[r][j], aa[r], bbp[j]);
    }

    // --- epilogue ---
    float bb[TN];
    #pragma unroll
    for (int j = 0; j < TN; j++) bb[j] = bias[tn * TN + j];

    #pragma unroll
    for (int r = 0; r < 8; r++) {
        int row0 = m0 + tm * 16 + 2 * r;
        float o0[TN], o1[TN];
        #pragma unroll
        for (int j = 0; j < TN; j++) {
            float2 v = unpack2(acc[r][j]);
            float u0 = v.x + bb[j];
            float u1 = v.y + bb[j];
            if (RELU) { u0 = fmaxf(u0, 0.f); u1 = fmaxf(u1, 0.f); }
            o0[j] = u0; o1[j] = u1;
        }
        if (row0 < N_NODES) {
            if (TN == 4)
                reinterpret_cast<float4*>(out + (size_t)row0 * NOUT)[tn] =
                    make_float4(o0[0], o0[1], o0[2], o0[3]);
            else
                reinterpret_cast<float2*>(out + (size_t)row0 * NOUT)[tn] =
                    make_float2(o0[0], o0[1]);
        }
        if (row0 + 1 < N_NODES) {
            if (TN == 4)
                reinterpret_cast<float4*>(out + (size_t)(row0 + 1) * NOUT)[tn] =
                    make_float4(o1[0], o1[1], o1[2], o1[3]);
            else
                reinterpret_cast<float2*>(out + (size_t)(row0 + 1) * NOUT)[tn] =
                    make_float2(o1[0], o1[1]);
        }
    }
}

// ---------------- launch ---------------------------------------------------
extern "C" void kernel_launch(void* const* d_in, const int* in_sizes, int n_in,
                              void* d_out, int out_size) {
    const float* x  = (const float*)d_in[0];
    const int*   ei = (const int*)  d_in[1];
    const float* W1 = (const float*)d_in[2];
    const float* b1 = (const float*)d_in[3];
    const float* W2 = (const float*)d_in[4];
    const float* b2 = (const float*)d_in[5];
    const float* W3 = (const float*)d_in[6];
    const float* b3 = (const float*)d_in[7];
    const float* W4 = (const float*)d_in[8];
    const float* b4 = (const float*)d_in[9];
    float* out = (float*)d_out;

    float *agg, *h1, *h2;
    cudaGetSymbolAddress((void**)&agg, g_agg4);
    cudaGetSymbolAddress((void**)&h1,  g_h1_4);
    cudaGetSymbolAddress((void**)&h2,  g_h2_4);

    const size_t smem128 = (size_t)(128 * 128 + 128 * 128) * sizeof(float); // 131072
    const size_t smem64  = (size_t)(128 * 128 + 128 * 64)  * sizeof(float); // 98304
    cudaFuncSetAttribute(mlp_kernel<128, true,  true >, cudaFuncAttributeMaxDynamicSharedMemorySize, (int)smem128);
    cudaFuncSetAttribute(mlp_kernel<128, true,  false>, cudaFuncAttributeMaxDynamicSharedMemorySize, (int)smem128);
    cudaFuncSetAttribute(mlp_kernel<64,  false, false>, cudaFuncAttributeMaxDynamicSharedMemorySize, (int)smem64);

    // 1) zero agg + deg
    {
        int n4 = (N_NODES * IN_DIM) / 4;
        zero_kernel<<<(n4 + 255) / 256, 256>>>();
    }
    // 2) scatter-add
    {
        long long threads = (long long)N_EDGES * 8;
        scatter_kernel<<<(int)((threads + 255) / 256), 256>>>(x, ei);
    }
    // 3) MLP (mean-division folded into layer-1 As fill)
    int gblocks = (N_NODES + 127) / 128;  // 782
    mlp_kernel<128, true,  true ><<<gblocks, 256, smem128>>>(x,  agg,     W1, b1, h1);
    mlp_kernel<128, true,  false><<<gblocks, 256, smem128>>>(h1, nullptr, W2, b2, h2);
    mlp_kernel<128, true,  false><<<gblocks, 256, smem128>>>(h2, nullptr, W3, b3, h1);
    mlp_kernel<64,  false, false><<<gblocks, 256, smem64 >>>(h1, nullptr, W4, b4, out);
}

// round 7
// speedup vs baseline: 1.1880x; 1.1880x over previous
#include <cuda_runtime.h>
#include <cuda_bf16.h>
#include <cstdint>

#define N_NODES 100000
#define N_EDGES 1250000
#define IN_DIM  64
#define HID     128
#define OUT_DIM 64

typedef unsigned long long ull;

// ---------------- scratch ---------------------------------------------------
__device__ float4 g_agg4[(size_t)N_NODES * IN_DIM / 4];   // 25.6 MB
__device__ float  g_deg [N_NODES];
// weight image: per layer [n][k] hi/lo bf16 planes, 256B rows, XOR swizzle
//  L0 hi@0 lo@32768 | L1 hi@65536 lo@98304 | L2 hi@131072 lo@163840 | L3 hi@196608 lo@212992
__device__ __align__(16) unsigned char g_wimg[229376];

// ---------------- helpers ---------------------------------------------------
__device__ __forceinline__ uint32_t smem_u32(const void* p) {
    uint32_t a;
    asm("{ .reg .u64 t; cvta.to.shared.u64 t, %1; cvt.u32.u64 %0, t; }" : "=r"(a) : "l"(p));
    return a;
}
// byte offset of bf16 element (row, col) inside one [rows][128] plane
__device__ __forceinline__ uint32_t phys(int row, int col) {
    return (uint32_t)row * 256u
         + (uint32_t)(((col >> 3) ^ (row & 7)) << 4)
         + (uint32_t)((col & 7) << 1);
}
__device__ __forceinline__ uint32_t bf2pack(float f0, float f1) {
    __nv_bfloat162 t = __floats2bfloat162_rn(f0, f1);   // low = f0
    return *reinterpret_cast<uint32_t*>(&t);
}
__device__ __forceinline__ void ldsm_x4(uint32_t* r, uint32_t addr) {
    asm volatile("ldmatrix.sync.aligned.m8n8.x4.shared.b16 {%0,%1,%2,%3}, [%4];"
                 : "=r"(r[0]), "=r"(r[1]), "=r"(r[2]), "=r"(r[3]) : "r"(addr));
}
__device__ __forceinline__ void mma_bf16(float* d, const uint32_t* a, uint32_t b0, uint32_t b1) {
    asm volatile(
        "mma.sync.aligned.m16n8k16.row.col.f32.bf16.bf16.f32 "
        "{%0,%1,%2,%3}, {%4,%5,%6,%7}, {%8,%9}, {%0,%1,%2,%3};"
        : "+f"(d[0]), "+f"(d[1]), "+f"(d[2]), "+f"(d[3])
        : "r"(a[0]), "r"(a[1]), "r"(a[2]), "r"(a[3]), "r"(b0), "r"(b1));
}
__device__ __forceinline__ void red_add_v4(float* p, float4 v) {
    asm volatile("red.global.add.v4.f32 [%0], {%1, %2, %3, %4};"
                 :: "l"(p), "f"(v.x), "f"(v.y), "f"(v.z), "f"(v.w) : "memory");
}

// ---------------- zero / scatter --------------------------------------------
__global__ void zero_kernel() {
    int i = blockIdx.x * blockDim.x + threadIdx.x;
    const int n4 = (N_NODES * IN_DIM) / 4;
    if (i < n4) g_agg4[i] = make_float4(0.f, 0.f, 0.f, 0.f);
    if (i < N_NODES) g_deg[i] = 0.f;
}
__global__ void scatter_kernel(const float* __restrict__ x, const int* __restrict__ ei) {
    long long t = (long long)blockIdx.x * blockDim.x + threadIdx.x;
    int e = (int)(t >> 3);
    if (e >= N_EDGES) return;
    int p = (int)(t & 7);
    int row = ei[e];
    int col = ei[N_EDGES + e];
    const float4* src = reinterpret_cast<const float4*>(x + (size_t)col * IN_DIM) + p * 2;
    float* dst = reinterpret_cast<float*>(g_agg4) + (size_t)row * IN_DIM + p * 8;
    float4 v0 = src[0];
    float4 v1 = src[1];
    red_add_v4(dst, v0);
    red_add_v4(dst + 4, v1);
    if (p == 0) atomicAdd(&g_deg[row], 1.0f);
}

// ---------------- weight prep: W[k][nout] -> [n][k] hi/lo planes ------------
__global__ void prep_weights(const float* __restrict__ W1, const float* __restrict__ W2,
                             const float* __restrict__ W3, const float* __restrict__ W4) {
    int t = blockIdx.x * blockDim.x + threadIdx.x;
    if (t >= 57344) return;
    const float* W; int e, nout; uint32_t hoff, psz;
    if      (t < 16384) { e = t;         W = W1; nout = 128; hoff = 0;      psz = 32768; }
    else if (t < 32768) { e = t - 16384; W = W2; nout = 128; hoff = 65536;  psz = 32768; }
    else if (t < 49152) { e = t - 32768; W = W3; nout = 128; hoff = 131072; psz = 32768; }
    else                { e = t - 49152; W = W4; nout = 64;  hoff = 196608; psz = 16384; }
    int n = e >> 7;          // output feature
    int k = e & 127;
    float w = W[k * nout + n];
    __nv_bfloat16 h = __float2bfloat16_rn(w);
    float res = w - __bfloat162float(h);
    __nv_bfloat16 l = __float2bfloat16_rn(res);
    uint32_t off = phys(n, k);
    *reinterpret_cast<__nv_bfloat16*>(g_wimg + hoff + off)       = h;
    *reinterpret_cast<__nv_bfloat16*>(g_wimg + hoff + psz + off) = l;
}

// ---------------- fused 4-layer MLP on HMMA ---------------------------------
#define SM_A_HI 0
#define SM_A_LO 32768
#define SM_W_HI 65536
#define SM_BIAS 131072              // 4 layers x 128 floats
#define SM_TOTAL (131072 + 2048)    // 133120

__global__ void __launch_bounds__(256, 1)
fused_mlp(const float* __restrict__ x,
          const float* __restrict__ b1, const float* __restrict__ b2,
          const float* __restrict__ b3, const float* __restrict__ b4,
          float* __restrict__ out) {
    extern __shared__ char smem[];
    uint32_t sb = smem_u32(smem);
    int tid = threadIdx.x, wid = tid >> 5, lane = tid & 31;
    int m0 = blockIdx.x * 128;

    float* bias_s = reinterpret_cast<float*>(smem + SM_BIAS);

    // ---- A fill: [x | agg/deg] -> hi/lo bf16 swizzled planes ----
    {
        int row  = tid >> 1;
        int half = tid & 1;
        int node = m0 + row;
        float inv = 1.0f;
        const float4* src;
        if (half == 0) {
            src = reinterpret_cast<const float4*>(x) + (size_t)(node < N_NODES ? node : 0) * 16;
        } else {
            src = g_agg4 + (size_t)(node < N_NODES ? node : 0) * 16;
            inv = 1.0f / fmaxf(g_deg[node < N_NODES ? node : 0], 1.0f);
        }
        #pragma unroll 4
        for (int q = 0; q < 16; q++) {
            float4 v = make_float4(0.f, 0.f, 0.f, 0.f);
            if (node < N_NODES) v = src[q];
            if (half) { v.x *= inv; v.y *= inv; v.z *= inv; v.w *= inv; }
            __nv_bfloat16 h0 = __float2bfloat16_rn(v.x), h1 = __float2bfloat16_rn(v.y);
            __nv_bfloat16 h2 = __float2bfloat16_rn(v.z), h3 = __float2bfloat16_rn(v.w);
            float r0 = v.x - __bfloat162float(h0), r1 = v.y - __bfloat162float(h1);
            float r2 = v.z - __bfloat162float(h2), r3 = v.w - __bfloat162float(h3);
            int c = half * 64 + q * 4;
            uint32_t off = phys(row, c);   // c&7 in {0,4}: 8B aligned
            ull hv = (ull)bf2pack(__bfloat162float(h0), __bfloat162float(h1))
                   | ((ull)bf2pack(__bfloat162float(h2), __bfloat162float(h3)) << 32);
            ull lv = (ull)bf2pack(r0, r1) | ((ull)bf2pack(r2, r3) << 32);
            *reinterpret_cast<ull*>(smem + SM_A_HI + off) = hv;
            *reinterpret_cast<ull*>(smem + SM_A_LO + off) = lv;
        }
        // biases (all layers once)
        if (tid < 128) {
            bias_s[tid]       = b1[tid];
            bias_s[128 + tid] = b2[tid];
            bias_s[256 + tid] = b3[tid];
            bias_s[384 + tid] = (tid < 64) ? b4[tid] : 0.f;
        }
    }
    // layer-0 weights
    {
        const float4* s = reinterpret_cast<const float4*>(g_wimg);
        float4* d = reinterpret_cast<float4*>(smem + SM_W_HI);
        for (int i = tid; i < 4096; i += 256) d[i] = s[i];
    }
    __syncthreads();

    const uint32_t hoffs[4] = {0, 65536, 131072, 196608};
    const int      nouts[4] = {128, 128, 128, 64};

    int warpM = wid >> 1;            // 0..3 -> 32-row slab
    int warpN = wid & 1;
    int mi    = lane >> 3;           // ldmatrix quadrant
    int lane8 = lane & 7;
    int g     = lane >> 2;
    int tt    = lane & 3;

    // per-thread ldmatrix A row components (fixed across layers)
    uint32_t arow_off[2]; int ar7[2]; int abit = mi >> 1;
    #pragma unroll
    for (int mt = 0; mt < 2; mt++) {
        int row = warpM * 32 + mt * 16 + (mi & 1) * 8 + lane8;
        arow_off[mt] = (uint32_t)row * 256u;
        ar7[mt] = row & 7;
    }

    for (int l = 0; l < 4; l++) {
        int nout   = nouts[l];
        int nbase  = warpN * (nout >> 1);
        int ntiles = nout >> 4;          // per-warp n-tiles: 8 or 4
        int pairs  = ntiles >> 1;        // 4 or 2
        uint32_t wlo = SM_W_HI + (uint32_t)nout * 256u;

        // B row components (depend on nout via nbase)
        uint32_t brow_off[4]; int br7[4]; int bbit = mi & 1;
        #pragma unroll
        for (int jp = 0; jp < 4; jp++) {
            int row = nbase + jp * 16 + (mi >> 1) * 8 + lane8;
            brow_off[jp] = (uint32_t)row * 256u;
            br7[jp] = row & 7;
        }

        float acc[2][8][4];
        #pragma unroll
        for (int mt = 0; mt < 2; mt++)
            #pragma unroll
            for (int j = 0; j < 8; j++)
                #pragma unroll
                for (int q = 0; q < 4; q++) acc[mt][j][q] = 0.f;

        for (int kc = 0; kc < 8; kc++) {
            uint32_t ah[2][4], al[2][4];
            #pragma unroll
            for (int mt = 0; mt < 2; mt++) {
                uint32_t off = arow_off[mt] + (uint32_t)((((kc << 1) + abit) ^ ar7[mt]) << 4);
                ldsm_x4(ah[mt], sb + SM_A_HI + off);
                ldsm_x4(al[mt], sb + SM_A_LO + off);
            }
            for (int jp = 0; jp < pairs; jp++) {
                uint32_t off = brow_off[jp] + (uint32_t)((((kc << 1) + bbit) ^ br7[jp]) << 4);
                uint32_t bh[4], bl[4];
                ldsm_x4(bh, sb + SM_W_HI + off);
                ldsm_x4(bl, sb + wlo + off);
                #pragma unroll
                for (int mt = 0; mt < 2; mt++) {
                    int j0 = jp * 2;
                    mma_bf16(acc[mt][j0],     ah[mt], bh[0], bh[1]);
                    mma_bf16(acc[mt][j0],     ah[mt], bl[0], bl[1]);
                    mma_bf16(acc[mt][j0],     al[mt], bh[0], bh[1]);
                    mma_bf16(acc[mt][j0 + 1], ah[mt], bh[2], bh[3]);
                    mma_bf16(acc[mt][j0 + 1], ah[mt], bl[2], bl[3]);
                    mma_bf16(acc[mt][j0 + 1], al[mt], bh[2], bh[3]);
                }
            }
        }
        __syncthreads();   // all A/W reads done before rewrite

        // ---- epilogue ----
        const float* bl_s = bias_s + l * 128;
        #pragma unroll
        for (int mt = 0; mt < 2; mt++) {
            int rg0 = warpM * 32 + mt * 16 + g;
            for (int j = 0; j < ntiles; j++) {
                int c0 = nbase + j * 8 + tt * 2;
                float bv0 = bl_s[c0], bv1 = bl_s[c0 + 1];
                float* d = acc[mt][j];
                if (l < 3) {
                    float f0 = fmaxf(d[0] + bv0, 0.f), f1 = fmaxf(d[1] + bv1, 0.f);
                    float f2 = fmaxf(d[2] + bv0, 0.f), f3 = fmaxf(d[3] + bv1, 0.f);
                    __nv_bfloat16 h0 = __float2bfloat16_rn(f0), h1 = __float2bfloat16_rn(f1);
                    __nv_bfloat16 h2 = __float2bfloat16_rn(f2), h3 = __float2bfloat16_rn(f3);
                    uint32_t o0 = phys(rg0, c0);
                    uint32_t o1 = phys(rg0 + 8, c0);
                    *reinterpret_cast<uint32_t*>(smem + SM_A_HI + o0) =
                        bf2pack(__bfloat162float(h0), __bfloat162float(h1));
                    *reinterpret_cast<uint32_t*>(smem + SM_A_LO + o0) =
                        bf2pack(f0 - __bfloat162float(h0), f1 - __bfloat162float(h1));
                    *reinterpret_cast<uint32_t*>(smem + SM_A_HI + o1) =
                        bf2pack(__bfloat162float(h2), __bfloat162float(h3));
                    *reinterpret_cast<uint32_t*>(smem + SM_A_LO + o1) =
                        bf2pack(f2 - __bfloat162float(h2), f3 - __bfloat162float(h3));
                } else {
                    int node0 = m0 + rg0;
                    int node1 = node0 + 8;
                    if (node0 < N_NODES)
                        *reinterpret_cast<float2*>(out + (size_t)node0 * OUT_DIM + c0) =
                            make_float2(d[0] + bv0, d[1] + bv1);
                    if (node1 < N_NODES)
                        *reinterpret_cast<float2*>(out + (size_t)node1 * OUT_DIM + c0) =
                            make_float2(d[2] + bv0, d[3] + bv1);
                }
            }
        }
        // next-layer weights (W reads for layer l finished at the barrier above)
        if (l < 3) {
            int nn = nouts[l + 1];
            const float4* s = reinterpret_cast<const float4*>(g_wimg + hoffs[l + 1]);
            float4* dst = reinterpret_cast<float4*>(smem + SM_W_HI);
            int q = nn * 32;
            for (int i = tid; i < q; i += 256) dst[i] = s[i];
        }
        __syncthreads();
    }
}

// ---------------- launch ----------------------------------------------------
extern "C" void kernel_launch(void* const* d_in, const int* in_sizes, int n_in,
                              void* d_out, int out_size) {
    const float* x  = (const float*)d_in[0];
    const int*   ei = (const int*)  d_in[1];
    const float* W1 = (const float*)d_in[2];
    const float* b1 = (const float*)d_in[3];
    const float* W2 = (const float*)d_in[4];
    const float* b2 = (const float*)d_in[5];
    const float* W3 = (const float*)d_in[6];
    const float* b3 = (const float*)d_in[7];
    const float* W4 = (const float*)d_in[8];
    const float* b4 = (const float*)d_in[9];
    float* out = (float*)d_out;

    cudaFuncSetAttribute(fused_mlp, cudaFuncAttributeMaxDynamicSharedMemorySize, SM_TOTAL);

    // 1) zero agg + deg
    {
        int n4 = (N_NODES * IN_DIM) / 4;
        zero_kernel<<<(n4 + 255) / 256, 256>>>();
    }
    // 2) scatter-add
    {
        long long threads = (long long)N_EDGES * 8;
        scatter_kernel<<<(int)((threads + 255) / 256), 256>>>(x, ei);
    }
    // 3) weight images
    prep_weights<<<(57344 + 255) / 256, 256>>>(W1, W2, W3, W4);
    // 4) fused 4-layer MLP on HMMA
    int gblocks = (N_NODES + 127) / 128;   // 782
    fused_mlp<<<gblocks, 256, SM_TOTAL>>>(x, b1, b2, b3, b4, out);
}

// round 8
// speedup vs baseline: 1.8321x; 1.5423x over previous
#include <cuda_runtime.h>
#include <cuda_bf16.h>
#include <cstdint>

#define N_NODES 100000
#define N_EDGES 1250000
#define IN_DIM  64
#define HID     128
#define OUT_DIM 64

typedef unsigned long long ull;

// ---------------- scratch ---------------------------------------------------
__device__ float4 g_agg4[(size_t)N_NODES * IN_DIM / 4];   // 25.6 MB
__device__ float  g_deg [N_NODES];
// weight image: per layer [n][k] hi/lo bf16 planes, 256B rows, XOR swizzle
__device__ __align__(16) unsigned char g_wimg[229376];

// ---------------- helpers ---------------------------------------------------
__device__ __forceinline__ uint32_t smem_u32(const void* p) {
    uint32_t a;
    asm("{ .reg .u64 t; cvta.to.shared.u64 t, %1; cvt.u32.u64 %0, t; }" : "=r"(a) : "l"(p));
    return a;
}
__device__ __forceinline__ uint32_t phys(int row, int col) {
    return (uint32_t)row * 256u
         + (uint32_t)(((col >> 3) ^ (row & 7)) << 4)
         + (uint32_t)((col & 7) << 1);
}
__device__ __forceinline__ uint32_t bf2pack(float f0, float f1) {
    __nv_bfloat162 t = __floats2bfloat162_rn(f0, f1);
    return *reinterpret_cast<uint32_t*>(&t);
}
__device__ __forceinline__ void ldsm_x4(uint32_t* r, uint32_t addr) {
    asm volatile("ldmatrix.sync.aligned.m8n8.x4.shared.b16 {%0,%1,%2,%3}, [%4];"
                 : "=r"(r[0]), "=r"(r[1]), "=r"(r[2]), "=r"(r[3]) : "r"(addr));
}
__device__ __forceinline__ void mma_bf16(float* d, const uint32_t* a, uint32_t b0, uint32_t b1) {
    asm volatile(
        "mma.sync.aligned.m16n8k16.row.col.f32.bf16.bf16.f32 "
        "{%0,%1,%2,%3}, {%4,%5,%6,%7}, {%8,%9}, {%0,%1,%2,%3};"
        : "+f"(d[0]), "+f"(d[1]), "+f"(d[2]), "+f"(d[3])
        : "r"(a[0]), "r"(a[1]), "r"(a[2]), "r"(a[3]), "r"(b0), "r"(b1));
}
__device__ __forceinline__ void red_add_v4(float* p, float4 v) {
    asm volatile("red.global.add.v4.f32 [%0], {%1, %2, %3, %4};"
                 :: "l"(p), "f"(v.x), "f"(v.y), "f"(v.z), "f"(v.w) : "memory");
}

// ---------------- zero / scatter --------------------------------------------
__global__ void zero_kernel() {
    int i = blockIdx.x * blockDim.x + threadIdx.x;
    const int n4 = (N_NODES * IN_DIM) / 4;
    if (i < n4) g_agg4[i] = make_float4(0.f, 0.f, 0.f, 0.f);
    if (i < N_NODES) g_deg[i] = 0.f;
}
__global__ void scatter_kernel(const float* __restrict__ x, const int* __restrict__ ei) {
    long long t = (long long)blockIdx.x * blockDim.x + threadIdx.x;
    int e = (int)(t >> 3);
    if (e >= N_EDGES) return;
    int p = (int)(t & 7);
    int row = ei[e];
    int col = ei[N_EDGES + e];
    const float4* src = reinterpret_cast<const float4*>(x + (size_t)col * IN_DIM) + p * 2;
    float* dst = reinterpret_cast<float*>(g_agg4) + (size_t)row * IN_DIM + p * 8;
    float4 v0 = src[0];
    float4 v1 = src[1];
    red_add_v4(dst, v0);
    red_add_v4(dst + 4, v1);
    if (p == 0) atomicAdd(&g_deg[row], 1.0f);
}

// ---------------- weight prep -----------------------------------------------
__global__ void prep_weights(const float* __restrict__ W1, const float* __restrict__ W2,
                             const float* __restrict__ W3, const float* __restrict__ W4) {
    int t = blockIdx.x * blockDim.x + threadIdx.x;
    if (t >= 57344) return;
    const float* W; int e, nout; uint32_t hoff, psz;
    if      (t < 16384) { e = t;         W = W1; nout = 128; hoff = 0;      psz = 32768; }
    else if (t < 32768) { e = t - 16384; W = W2; nout = 128; hoff = 65536;  psz = 32768; }
    else if (t < 49152) { e = t - 32768; W = W3; nout = 128; hoff = 131072; psz = 32768; }
    else                { e = t - 49152; W = W4; nout = 64;  hoff = 196608; psz = 16384; }
    int n = e >> 7;
    int k = e & 127;
    float w = W[k * nout + n];
    __nv_bfloat16 h = __float2bfloat16_rn(w);
    float res = w - __bfloat162float(h);
    __nv_bfloat16 l = __float2bfloat16_rn(res);
    uint32_t off = phys(n, k);
    *reinterpret_cast<__nv_bfloat16*>(g_wimg + hoff + off)       = h;
    *reinterpret_cast<__nv_bfloat16*>(g_wimg + hoff + psz + off) = l;
}

// ---------------- fused 4-layer MLP on HMMA ---------------------------------
#define SM_A_HI 0
#define SM_A_LO 32768
#define SM_W_HI 65536
#define SM_BIAS 131072
#define SM_TOTAL (131072 + 2048)

// One layer: mainloop (reads A/W smem) -> sync -> epilogue (writes A smem or out).
// Fully compile-time NOUT so every loop unrolls.
template<int NOUT, bool LAST>
__device__ __forceinline__ void layer_body(char* smem, uint32_t sb, float* __restrict__ out,
                                           int wid, int lane, int m0, const float* bl_s) {
    constexpr int NTILES = NOUT >> 4;      // per-warp n16 tiles (8 or 4)
    constexpr int PAIRS  = NTILES >> 1;    // ldsm.x4 B pairs (4 or 2)
    const uint32_t wlo = SM_W_HI + (uint32_t)NOUT * 256u;

    int warpM = wid >> 1;
    int warpN = wid & 1;
    int mi    = lane >> 3;
    int lane8 = lane & 7;
    int g     = lane >> 2;
    int tt    = lane & 3;
    int nbase = warpN * (NOUT >> 1);

    uint32_t arow_off[2]; int ar7[2]; int abit = mi >> 1;
    #pragma unroll
    for (int mt = 0; mt < 2; mt++) {
        int row = warpM * 32 + mt * 16 + (mi & 1) * 8 + lane8;
        arow_off[mt] = (uint32_t)row * 256u;
        ar7[mt] = row & 7;
    }
    uint32_t brow_off[PAIRS]; int br7[PAIRS]; int bbit = mi & 1;
    #pragma unroll
    for (int jp = 0; jp < PAIRS; jp++) {
        int row = nbase + jp * 16 + (mi >> 1) * 8 + lane8;
        brow_off[jp] = (uint32_t)row * 256u;
        br7[jp] = row & 7;
    }

    float acc[2][NTILES][4];
    #pragma unroll
    for (int mt = 0; mt < 2; mt++)
        #pragma unroll
        for (int j = 0; j < NTILES; j++)
            #pragma unroll
            for (int q = 0; q < 4; q++) acc[mt][j][q] = 0.f;

    #pragma unroll
    for (int kc = 0; kc < 8; kc++) {
        uint32_t ah[2][4], al[2][4];
        #pragma unroll
        for (int mt = 0; mt < 2; mt++) {
            uint32_t off = arow_off[mt] + (uint32_t)((((kc << 1) + abit) ^ ar7[mt]) << 4);
            ldsm_x4(ah[mt], sb + SM_A_HI + off);
            ldsm_x4(al[mt], sb + SM_A_LO + off);
        }
        uint32_t bh[PAIRS][4], bl[PAIRS][4];
        #pragma unroll
        for (int jp = 0; jp < PAIRS; jp++) {
            uint32_t off = brow_off[jp] + (uint32_t)((((kc << 1) + bbit) ^ br7[jp]) << 4);
            ldsm_x4(bh[jp], sb + SM_W_HI + off);
            ldsm_x4(bl[jp], sb + wlo + off);
        }
        #pragma unroll
        for (int jp = 0; jp < PAIRS; jp++) {
            #pragma unroll
            for (int mt = 0; mt < 2; mt++) {
                int j0 = jp * 2;
                mma_bf16(acc[mt][j0],     ah[mt], bh[jp][0], bh[jp][1]);
                mma_bf16(acc[mt][j0 + 1], ah[mt], bh[jp][2], bh[jp][3]);
                mma_bf16(acc[mt][j0],     ah[mt], bl[jp][0], bl[jp][1]);
                mma_bf16(acc[mt][j0 + 1], ah[mt], bl[jp][2], bl[jp][3]);
                mma_bf16(acc[mt][j0],     al[mt], bh[jp][0], bh[jp][1]);
                mma_bf16(acc[mt][j0 + 1], al[mt], bh[jp][2], bh[jp][3]);
            }
        }
    }
    __syncthreads();   // all A/W smem reads complete before epilogue rewrites A

    #pragma unroll
    for (int mt = 0; mt < 2; mt++) {
        int rg0 = warpM * 32 + mt * 16 + g;
        #pragma unroll
        for (int j = 0; j < NTILES; j++) {
            int c0 = nbase + j * 8 + tt * 2;
            float bv0 = bl_s[c0], bv1 = bl_s[c0 + 1];
            float* d = acc[mt][j];
            if (!LAST) {
                float f0 = fmaxf(d[0] + bv0, 0.f), f1 = fmaxf(d[1] + bv1, 0.f);
                float f2 = fmaxf(d[2] + bv0, 0.f), f3 = fmaxf(d[3] + bv1, 0.f);
                __nv_bfloat16 h0 = __float2bfloat16_rn(f0), h1 = __float2bfloat16_rn(f1);
                __nv_bfloat16 h2 = __float2bfloat16_rn(f2), h3 = __float2bfloat16_rn(f3);
                uint32_t o0 = phys(rg0, c0);
                uint32_t o1 = phys(rg0 + 8, c0);
                *reinterpret_cast<uint32_t*>(smem + SM_A_HI + o0) =
                    bf2pack(__bfloat162float(h0), __bfloat162float(h1));
                *reinterpret_cast<uint32_t*>(smem + SM_A_LO + o0) =
                    bf2pack(f0 - __bfloat162float(h0), f1 - __bfloat162float(h1));
                *reinterpret_cast<uint32_t*>(smem + SM_A_HI + o1) =
                    bf2pack(__bfloat162float(h2), __bfloat162float(h3));
                *reinterpret_cast<uint32_t*>(smem + SM_A_LO + o1) =
                    bf2pack(f2 - __bfloat162float(h2), f3 - __bfloat162float(h3));
            } else {
                int node0 = m0 + rg0;
                int node1 = node0 + 8;
                if (node0 < N_NODES)
                    *reinterpret_cast<float2*>(out + (size_t)node0 * OUT_DIM + c0) =
                        make_float2(d[0] + bv0, d[1] + bv1);
                if (node1 < N_NODES)
                    *reinterpret_cast<float2*>(out + (size_t)node1 * OUT_DIM + c0) =
                        make_float2(d[2] + bv0, d[3] + bv1);
            }
        }
    }
}

__device__ __forceinline__ void copy_weights(char* smem, int tid, uint32_t hoff, int nfloat4) {
    const float4* s = reinterpret_cast<const float4*>(g_wimg + hoff);
    float4* d = reinterpret_cast<float4*>(smem + SM_W_HI);
    for (int i = tid; i < nfloat4; i += 256) d[i] = s[i];
}

__global__ void __launch_bounds__(256, 1)
fused_mlp(const float* __restrict__ x,
          const float* __restrict__ b1, const float* __restrict__ b2,
          const float* __restrict__ b3, const float* __restrict__ b4,
          float* __restrict__ out) {
    extern __shared__ char smem[];
    uint32_t sb = smem_u32(smem);
    int tid = threadIdx.x, wid = tid >> 5, lane = tid & 31;
    int m0 = blockIdx.x * 128;

    float* bias_s = reinterpret_cast<float*>(smem + SM_BIAS);

    // ---- A fill ----
    {
        int row  = tid >> 1;
        int half = tid & 1;
        int node = m0 + row;
        float inv = 1.0f;
        const float4* src;
        if (half == 0) {
            src = reinterpret_cast<const float4*>(x) + (size_t)(node < N_NODES ? node : 0) * 16;
        } else {
            src = g_agg4 + (size_t)(node < N_NODES ? node : 0) * 16;
            inv = 1.0f / fmaxf(g_deg[node < N_NODES ? node : 0], 1.0f);
        }
        #pragma unroll 4
        for (int q = 0; q < 16; q++) {
            float4 v = make_float4(0.f, 0.f, 0.f, 0.f);
            if (node < N_NODES) v = src[q];
            if (half) { v.x *= inv; v.y *= inv; v.z *= inv; v.w *= inv; }
            __nv_bfloat16 h0 = __float2bfloat16_rn(v.x), h1 = __float2bfloat16_rn(v.y);
            __nv_bfloat16 h2 = __float2bfloat16_rn(v.z), h3 = __float2bfloat16_rn(v.w);
            float r0 = v.x - __bfloat162float(h0), r1 = v.y - __bfloat162float(h1);
            float r2 = v.z - __bfloat162float(h2), r3 = v.w - __bfloat162float(h3);
            int c = half * 64 + q * 4;
            uint32_t off = phys(row, c);
            ull hv = (ull)bf2pack(__bfloat162float(h0), __bfloat162float(h1))
                   | ((ull)bf2pack(__bfloat162float(h2), __bfloat162float(h3)) << 32);
            ull lv = (ull)bf2pack(r0, r1) | ((ull)bf2pack(r2, r3) << 32);
            *reinterpret_cast<ull*>(smem + SM_A_HI + off) = hv;
            *reinterpret_cast<ull*>(smem + SM_A_LO + off) = lv;
        }
        if (tid < 128) {
            bias_s[tid]       = b1[tid];
            bias_s[128 + tid] = b2[tid];
            bias_s[256 + tid] = b3[tid];
            bias_s[384 + tid] = (tid < 64) ? b4[tid] : 0.f;
        }
    }
    copy_weights(smem, tid, 0, 4096);
    __syncthreads();

    layer_body<128, false>(smem, sb, out, wid, lane, m0, bias_s);
    copy_weights(smem, tid, 65536, 4096);
    __syncthreads();

    layer_body<128, false>(smem, sb, out, wid, lane, m0, bias_s + 128);
    copy_weights(smem, tid, 131072, 4096);
    __syncthreads();

    layer_body<128, false>(smem, sb, out, wid, lane, m0, bias_s + 256);
    copy_weights(smem, tid, 196608, 2048);
    __syncthreads();

    layer_body<64, true>(smem, sb, out, wid, lane, m0, bias_s + 384);
}

// ---------------- launch ----------------------------------------------------
extern "C" void kernel_launch(void* const* d_in, const int* in_sizes, int n_in,
                              void* d_out, int out_size) {
    const float* x  = (const float*)d_in[0];
    const int*   ei = (const int*)  d_in[1];
    const float* W1 = (const float*)d_in[2];
    const float* b1 = (const float*)d_in[3];
    const float* W2 = (const float*)d_in[4];
    const float* b2 = (const float*)d_in[5];
    const float* W3 = (const float*)d_in[6];
    const float* b3 = (const float*)d_in[7];
    const float* W4 = (const float*)d_in[8];
    const float* b4 = (const float*)d_in[9];
    float* out = (float*)d_out;

    cudaFuncSetAttribute(fused_mlp, cudaFuncAttributeMaxDynamicSharedMemorySize, SM_TOTAL);

    {
        int n4 = (N_NODES * IN_DIM) / 4;
        zero_kernel<<<(n4 + 255) / 256, 256>>>();
    }
    {
        long long threads = (long long)N_EDGES * 8;
        scatter_kernel<<<(int)((threads + 255) / 256), 256>>>(x, ei);
    }
    prep_weights<<<(57344 + 255) / 256, 256>>>(W1, W2, W3, W4);
    int gblocks = (N_NODES + 127) / 128;   // 782
    fused_mlp<<<gblocks, 256, SM_TOTAL>>>(x, b1, b2, b3, b4, out);
}

// round 10
// speedup vs baseline: 1.9164x; 1.0460x over previous
#include <cuda_runtime.h>
#include <cuda_bf16.h>
#include <cstdint>

#define N_NODES 100000
#define N_EDGES 1250000
#define IN_DIM  64
#define HID     128
#define OUT_DIM 64

typedef unsigned long long ull;

// ---------------- scratch ---------------------------------------------------
__device__ float4 g_agg4[(size_t)N_NODES * IN_DIM / 4];   // 25.6 MB
__device__ float  g_deg [N_NODES];
// weight image: per layer [n][k] hi/lo bf16 planes, 256B rows, XOR swizzle
__device__ __align__(16) unsigned char g_wimg[229376];

// ---------------- helpers ---------------------------------------------------
__device__ __forceinline__ uint32_t smem_u32(const void* p) {
    uint32_t a;
    asm("{ .reg .u64 t; cvta.to.shared.u64 t, %1; cvt.u32.u64 %0, t; }" : "=r"(a) : "l"(p));
    return a;
}
__device__ __forceinline__ uint32_t phys(int row, int col) {
    return (uint32_t)row * 256u
         + (uint32_t)(((col >> 3) ^ (row & 7)) << 4)
         + (uint32_t)((col & 7) << 1);
}
__device__ __forceinline__ uint32_t bf2pack(float f0, float f1) {
    __nv_bfloat162 t = __floats2bfloat162_rn(f0, f1);
    return *reinterpret_cast<uint32_t*>(&t);
}
__device__ __forceinline__ void ldsm_x4(uint32_t* r, uint32_t addr) {
    asm volatile("ldmatrix.sync.aligned.m8n8.x4.shared.b16 {%0,%1,%2,%3}, [%4];"
                 : "=r"(r[0]), "=r"(r[1]), "=r"(r[2]), "=r"(r[3]) : "r"(addr));
}
__device__ __forceinline__ void mma_bf16(float* d, const uint32_t* a, uint32_t b0, uint32_t b1) {
    asm volatile(
        "mma.sync.aligned.m16n8k16.row.col.f32.bf16.bf16.f32 "
        "{%0,%1,%2,%3}, {%4,%5,%6,%7}, {%8,%9}, {%0,%1,%2,%3};"
        : "+f"(d[0]), "+f"(d[1]), "+f"(d[2]), "+f"(d[3])
        : "r"(a[0]), "r"(a[1]), "r"(a[2]), "r"(a[3]), "r"(b0), "r"(b1));
}
__device__ __forceinline__ void red_add_v4(float* p, float4 v) {
    asm volatile("red.global.add.v4.f32 [%0], {%1, %2, %3, %4};"
                 :: "l"(p), "f"(v.x), "f"(v.y), "f"(v.z), "f"(v.w) : "memory");
}

// ---------------- zero / scatter --------------------------------------------
__global__ void zero_kernel() {
    int i = blockIdx.x * blockDim.x + threadIdx.x;
    const int n4 = (N_NODES * IN_DIM) / 4;
    if (i < n4) g_agg4[i] = make_float4(0.f, 0.f, 0.f, 0.f);
    if (i < N_NODES) g_deg[i] = 0.f;
}
__global__ void scatter_kernel(const float* __restrict__ x, const int* __restrict__ ei) {
    long long t = (long long)blockIdx.x * blockDim.x + threadIdx.x;
    int e = (int)(t >> 3);
    if (e >= N_EDGES) return;
    int p = (int)(t & 7);
    int row = ei[e];
    int col = ei[N_EDGES + e];
    const float4* src = reinterpret_cast<const float4*>(x + (size_t)col * IN_DIM) + p * 2;
    float* dst = reinterpret_cast<float*>(g_agg4) + (size_t)row * IN_DIM + p * 8;
    float4 v0 = src[0];
    float4 v1 = src[1];
    red_add_v4(dst, v0);
    red_add_v4(dst + 4, v1);
    if (p == 0) atomicAdd(&g_deg[row], 1.0f);
}

// ---------------- weight prep -----------------------------------------------
__global__ void prep_weights(const float* __restrict__ W1, const float* __restrict__ W2,
                             const float* __restrict__ W3, const float* __restrict__ W4) {
    int t = blockIdx.x * blockDim.x + threadIdx.x;
    if (t >= 57344) return;
    const float* W; int e, nout; uint32_t hoff, psz;
    if      (t < 16384) { e = t;         W = W1; nout = 128; hoff = 0;      psz = 32768; }
    else if (t < 32768) { e = t - 16384; W = W2; nout = 128; hoff = 65536;  psz = 32768; }
    else if (t < 49152) { e = t - 32768; W = W3; nout = 128; hoff = 131072; psz = 32768; }
    else                { e = t - 49152; W = W4; nout = 64;  hoff = 196608; psz = 16384; }
    int n = e >> 7;
    int k = e & 127;
    float w = W[k * nout + n];
    __nv_bfloat16 h = __float2bfloat16_rn(w);
    float res = w - __bfloat162float(h);
    __nv_bfloat16 l = __float2bfloat16_rn(res);
    uint32_t off = phys(n, k);
    *reinterpret_cast<__nv_bfloat16*>(g_wimg + hoff + off)       = h;
    *reinterpret_cast<__nv_bfloat16*>(g_wimg + hoff + psz + off) = l;
}

// ---------------- fused 4-layer MLP on HMMA, BM=64, 2 CTAs/SM ---------------
#define SM_A_HI 0
#define SM_A_LO 16384
#define SM_W_HI 32768
#define SM_BIAS 98304
#define SM_TOTAL (98304 + 2048)     // 100352 bytes -> 2 CTAs/SM

// Warp tile = 32 cols always (NTILES=4, PAIRS=2).
// NOUT=128: warpM=wid>>2 (2 x 32 rows, MT=2), warpN=wid&3 (4 x 32 cols)
// NOUT=64 : warpM=wid>>1 (4 x 16 rows, MT=1), warpN=wid&1 (2 x 32 cols)
template<int NOUT, bool LAST>
__device__ __forceinline__ void layer_body(char* smem, uint32_t sb, float* __restrict__ out,
                                           int wid, int lane, int m0, const float* bl_s) {
    constexpr int MT = (NOUT == 128) ? 2 : 1;
    const uint32_t wlo = SM_W_HI + (uint32_t)NOUT * 256u;

    int warpM = (NOUT == 128) ? (wid >> 2) : (wid >> 1);
    int warpN = (NOUT == 128) ? (wid & 3) : (wid & 1);
    int mi    = lane >> 3;
    int lane8 = lane & 7;
    int g     = lane >> 2;
    int tt    = lane & 3;
    int nbase = warpN * 32;

    uint32_t arow_off[MT]; int ar7[MT]; int abit = mi >> 1;
    #pragma unroll
    for (int mt = 0; mt < MT; mt++) {
        int row = warpM * (MT * 16) + mt * 16 + (mi & 1) * 8 + lane8;
        arow_off[mt] = (uint32_t)row * 256u;
        ar7[mt] = row & 7;
    }
    uint32_t brow_off[2]; int br7[2]; int bbit = mi & 1;
    #pragma unroll
    for (int jp = 0; jp < 2; jp++) {
        int row = nbase + jp * 16 + (mi >> 1) * 8 + lane8;
        brow_off[jp] = (uint32_t)row * 256u;
        br7[jp] = row & 7;
    }

    float acc[MT][4][4];
    #pragma unroll
    for (int mt = 0; mt < MT; mt++)
        #pragma unroll
        for (int j = 0; j < 4; j++)
            #pragma unroll
            for (int q = 0; q < 4; q++) acc[mt][j][q] = 0.f;

    #pragma unroll
    for (int kc = 0; kc < 8; kc++) {
        uint32_t ah[MT][4], al[MT][4];
        #pragma unroll
        for (int mt = 0; mt < MT; mt++) {
            uint32_t off = arow_off[mt] + (uint32_t)((((kc << 1) + abit) ^ ar7[mt]) << 4);
            ldsm_x4(ah[mt], sb + SM_A_HI + off);
            ldsm_x4(al[mt], sb + SM_A_LO + off);
        }
        uint32_t bh[2][4], bl[2][4];
        #pragma unroll
        for (int jp = 0; jp < 2; jp++) {
            uint32_t off = brow_off[jp] + (uint32_t)((((kc << 1) + bbit) ^ br7[jp]) << 4);
            ldsm_x4(bh[jp], sb + SM_W_HI + off);
            ldsm_x4(bl[jp], sb + wlo + off);
        }
        #pragma unroll
        for (int jp = 0; jp < 2; jp++) {
            #pragma unroll
            for (int mt = 0; mt < MT; mt++) {
                int j0 = jp * 2;
                mma_bf16(acc[mt][j0],     ah[mt], bh[jp][0], bh[jp][1]);
                mma_bf16(acc[mt][j0 + 1], ah[mt], bh[jp][2], bh[jp][3]);
                mma_bf16(acc[mt][j0],     ah[mt], bl[jp][0], bl[jp][1]);
                mma_bf16(acc[mt][j0 + 1], ah[mt], bl[jp][2], bl[jp][3]);
                mma_bf16(acc[mt][j0],     al[mt], bh[jp][0], bh[jp][1]);
                mma_bf16(acc[mt][j0 + 1], al[mt], bh[jp][2], bh[jp][3]);
            }
        }
    }
    __syncthreads();   // all A/W smem reads complete before epilogue rewrites A

    #pragma unroll
    for (int mt = 0; mt < MT; mt++) {
        int rg0 = warpM * (MT * 16) + mt * 16 + g;
        #pragma unroll
        for (int j = 0; j < 4; j++) {
            int c0 = nbase + j * 8 + tt * 2;
            float bv0 = bl_s[c0], bv1 = bl_s[c0 + 1];
            float* d = acc[mt][j];
            if (!LAST) {
                float f0 = fmaxf(d[0] + bv0, 0.f), f1 = fmaxf(d[1] + bv1, 0.f);
                float f2 = fmaxf(d[2] + bv0, 0.f), f3 = fmaxf(d[3] + bv1, 0.f);
                __nv_bfloat16 h0 = __float2bfloat16_rn(f0), h1 = __float2bfloat16_rn(f1);
                __nv_bfloat16 h2 = __float2bfloat16_rn(f2), h3 = __float2bfloat16_rn(f3);
                uint32_t o0 = phys(rg0, c0);
                uint32_t o1 = phys(rg0 + 8, c0);
                *reinterpret_cast<uint32_t*>(smem + SM_A_HI + o0) =
                    bf2pack(__bfloat162float(h0), __bfloat162float(h1));
                *reinterpret_cast<uint32_t*>(smem + SM_A_LO + o0) =
                    bf2pack(f0 - __bfloat162float(h0), f1 - __bfloat162float(h1));
                *reinterpret_cast<uint32_t*>(smem + SM_A_HI + o1) =
                    bf2pack(__bfloat162float(h2), __bfloat162float(h3));
                *reinterpret_cast<uint32_t*>(smem + SM_A_LO + o1) =
                    bf2pack(f2 - __bfloat162float(h2), f3 - __bfloat162float(h3));
            } else {
                int node0 = m0 + rg0;
                int node1 = node0 + 8;
                if (node0 < N_NODES)
                    *reinterpret_cast<float2*>(out + (size_t)node0 * OUT_DIM + c0) =
                        make_float2(d[0] + bv0, d[1] + bv1);
                if (node1 < N_NODES)
                    *reinterpret_cast<float2*>(out + (size_t)node1 * OUT_DIM + c0) =
                        make_float2(d[2] + bv0, d[3] + bv1);
            }
        }
    }
}

__device__ __forceinline__ void copy_weights(char* smem, int tid, uint32_t hoff, int nfloat4) {
    const float4* s = reinterpret_cast<const float4*>(g_wimg + hoff);
    float4* d = reinterpret_cast<float4*>(smem + SM_W_HI);
    for (int i = tid; i < nfloat4; i += 256) d[i] = s[i];
}

__global__ void __launch_bounds__(256, 2)
fused_mlp(const float* __restrict__ x,
          const float* __restrict__ b1, const float* __restrict__ b2,
          const float* __restrict__ b3, const float* __restrict__ b4,
          float* __restrict__ out) {
    extern __shared__ char smem[];
    uint32_t sb = smem_u32(smem);
    int tid = threadIdx.x, wid = tid >> 5, lane = tid & 31;
    int m0 = blockIdx.x * 64;

    float* bias_s = reinterpret_cast<float*>(smem + SM_BIAS);

    // ---- A fill: 64 rows x (x | agg/deg); 4 threads per row ----
    {
        int row = tid >> 2;
        int sub = tid & 3;
        int node = m0 + row;
        int nsafe = node < N_NODES ? node : 0;
        float inv = 1.0f;
        const float4* src;
        if (sub < 2) src = reinterpret_cast<const float4*>(x) + (size_t)nsafe * 16;
        else {
            src = g_agg4 + (size_t)nsafe * 16;
            inv = 1.0f / fmaxf(g_deg[nsafe], 1.0f);
        }
        #pragma unroll
        for (int q = 0; q < 8; q++) {
            float4 v = make_float4(0.f, 0.f, 0.f, 0.f);
            if (node < N_NODES) v = src[(sub & 1) * 8 + q];
            if (sub >= 2) { v.x *= inv; v.y *= inv; v.z *= inv; v.w *= inv; }
            __nv_bfloat16 h0 = __float2bfloat16_rn(v.x), h1 = __float2bfloat16_rn(v.y);
            __nv_bfloat16 h2 = __float2bfloat16_rn(v.z), h3 = __float2bfloat16_rn(v.w);
            float r0 = v.x - __bfloat162float(h0), r1 = v.y - __bfloat162float(h1);
            float r2 = v.z - __bfloat162float(h2), r3 = v.w - __bfloat162float(h3);
            int c = sub * 32 + q * 4;
            uint32_t off = phys(row, c);
            ull hv = (ull)bf2pack(__bfloat162float(h0), __bfloat162float(h1))
                   | ((ull)bf2pack(__bfloat162float(h2), __bfloat162float(h3)) << 32);
            ull lv = (ull)bf2pack(r0, r1) | ((ull)bf2pack(r2, r3) << 32);
            *reinterpret_cast<ull*>(smem + SM_A_HI + off) = hv;
            *reinterpret_cast<ull*>(smem + SM_A_LO + off) = lv;
        }
        if (tid < 128) {
            bias_s[tid]       = b1[tid];
            bias_s[128 + tid] = b2[tid];
            bias_s[256 + tid] = b3[tid];
            bias_s[384 + tid] = (tid < 64) ? b4[tid] : 0.f;
        }
    }
    copy_weights(smem, tid, 0, 4096);
    __syncthreads();

    layer_body<128, false>(smem, sb, out, wid, lane, m0, bias_s);
    copy_weights(smem, tid, 65536, 4096);
    __syncthreads();

    layer_body<128, false>(smem, sb, out, wid, lane, m0, bias_s + 128);
    copy_weights(smem, tid, 131072, 4096);
    __syncthreads();

    layer_body<128, false>(smem, sb, out, wid, lane, m0, bias_s + 256);
    copy_weights(smem, tid, 196608, 2048);
    __syncthreads();

    layer_body<64, true>(smem, sb, out, wid, lane, m0, bias_s + 384);
}

// ---------------- launch ----------------------------------------------------
extern "C" void kernel_launch(void* const* d_in, const int* in_sizes, int n_in,
                              void* d_out, int out_size) {
    const float* x  = (const float*)d_in[0];
    const int*   ei = (const int*)  d_in[1];
    const float* W1 = (const float*)d_in[2];
    const float* b1 = (const float*)d_in[3];
    const float* W2 = (const float*)d_in[4];
    const float* b2 = (const float*)d_in[5];
    const float* W3 = (const float*)d_in[6];
    const float* b3 = (const float*)d_in[7];
    const float* W4 = (const float*)d_in[8];
    const float* b4 = (const float*)d_in[9];
    float* out = (float*)d_out;

    cudaFuncSetAttribute(fused_mlp, cudaFuncAttributeMaxDynamicSharedMemorySize, SM_TOTAL);

    {
        int n4 = (N_NODES * IN_DIM) / 4;
        zero_kernel<<<(n4 + 255) / 256, 256>>>();
    }
    {
        long long threads = (long long)N_EDGES * 8;
        scatter_kernel<<<(int)((threads + 255) / 256), 256>>>(x, ei);
    }
    prep_weights<<<(57344 + 255) / 256, 256>>>(W1, W2, W3, W4);
    int gblocks = (N_NODES + 63) / 64;   // 1563
    fused_mlp<<<gblocks, 256, SM_TOTAL>>>(x, b1, b2, b3, b4, out);
}

// round 11
// speedup vs baseline: 2.4830x; 1.2957x over previous
#include <cuda_runtime.h>
#include <cuda_bf16.h>
#include <cstdint>

#define N_NODES 100000
#define N_EDGES 1250000
#define IN_DIM  64
#define HID     128
#define OUT_DIM 64

typedef unsigned long long ull;

// ---------------- scratch ---------------------------------------------------
__device__ float4 g_agg4[(size_t)N_NODES * IN_DIM / 4];   // 25.6 MB
__device__ float  g_deg [N_NODES];
// weight image: per layer [n][k] hi/lo bf16 planes, 256B rows, XOR swizzle
__device__ __align__(16) unsigned char g_wimg[229376];

// ---------------- helpers ---------------------------------------------------
__device__ __forceinline__ uint32_t smem_u32(const void* p) {
    uint32_t a;
    asm("{ .reg .u64 t; cvta.to.shared.u64 t, %1; cvt.u32.u64 %0, t; }" : "=r"(a) : "l"(p));
    return a;
}
__device__ __forceinline__ uint32_t phys(int row, int col) {
    return (uint32_t)row * 256u
         + (uint32_t)(((col >> 3) ^ (row & 7)) << 4)
         + (uint32_t)((col & 7) << 1);
}
__device__ __forceinline__ uint32_t bf2pack(float f0, float f1) {
    __nv_bfloat162 t = __floats2bfloat162_rn(f0, f1);
    return *reinterpret_cast<uint32_t*>(&t);
}
__device__ __forceinline__ void ldsm_x4(uint32_t* r, uint32_t addr) {
    asm volatile("ldmatrix.sync.aligned.m8n8.x4.shared.b16 {%0,%1,%2,%3}, [%4];"
                 : "=r"(r[0]), "=r"(r[1]), "=r"(r[2]), "=r"(r[3]) : "r"(addr));
}
__device__ __forceinline__ void mma_bf16(float* d, const uint32_t* a, uint32_t b0, uint32_t b1) {
    asm volatile(
        "mma.sync.aligned.m16n8k16.row.col.f32.bf16.bf16.f32 "
        "{%0,%1,%2,%3}, {%4,%5,%6,%7}, {%8,%9}, {%0,%1,%2,%3};"
        : "+f"(d[0]), "+f"(d[1]), "+f"(d[2]), "+f"(d[3])
        : "r"(a[0]), "r"(a[1]), "r"(a[2]), "r"(a[3]), "r"(b0), "r"(b1));
}
__device__ __forceinline__ void red_add_v4(float* p, float4 v) {
    asm volatile("red.global.add.v4.f32 [%0], {%1, %2, %3, %4};"
                 :: "l"(p), "f"(v.x), "f"(v.y), "f"(v.z), "f"(v.w) : "memory");
}
__device__ __forceinline__ void cp16(uint32_t dst, const void* src) {
    asm volatile("cp.async.cg.shared.global [%0], [%1], 16;" :: "r"(dst), "l"(src));
}
#define CP_COMMIT() asm volatile("cp.async.commit_group;" ::: "memory")
#define CP_WAIT0()  asm volatile("cp.async.wait_group 0;" ::: "memory")

// ---------------- zero / scatter --------------------------------------------
__global__ void zero_kernel() {
    int i = blockIdx.x * blockDim.x + threadIdx.x;
    const int n4 = (N_NODES * IN_DIM) / 4;
    if (i < n4) g_agg4[i] = make_float4(0.f, 0.f, 0.f, 0.f);
    if (i < N_NODES) g_deg[i] = 0.f;
}
__global__ void scatter_kernel(const float* __restrict__ x, const int* __restrict__ ei) {
    long long t = (long long)blockIdx.x * blockDim.x + threadIdx.x;
    int e = (int)(t >> 3);
    if (e >= N_EDGES) return;
    int p = (int)(t & 7);
    int row = ei[e];
    int col = ei[N_EDGES + e];
    const float4* src = reinterpret_cast<const float4*>(x + (size_t)col * IN_DIM) + p * 2;
    float* dst = reinterpret_cast<float*>(g_agg4) + (size_t)row * IN_DIM + p * 8;
    float4 v0 = src[0];
    float4 v1 = src[1];
    red_add_v4(dst, v0);
    red_add_v4(dst + 4, v1);
    if (p == 0) atomicAdd(&g_deg[row], 1.0f);
}

// ---------------- weight prep -----------------------------------------------
__global__ void prep_weights(const float* __restrict__ W1, const float* __restrict__ W2,
                             const float* __restrict__ W3, const float* __restrict__ W4) {
    int t = blockIdx.x * blockDim.x + threadIdx.x;
    if (t >= 57344) return;
    const float* W; int e, nout; uint32_t hoff, psz;
    if      (t < 16384) { e = t;         W = W1; nout = 128; hoff = 0;      psz = 32768; }
    else if (t < 32768) { e = t - 16384; W = W2; nout = 128; hoff = 65536;  psz = 32768; }
    else if (t < 49152) { e = t - 32768; W = W3; nout = 128; hoff = 131072; psz = 32768; }
    else                { e = t - 49152; W = W4; nout = 64;  hoff = 196608; psz = 16384; }
    int n = e >> 7;
    int k = e & 127;
    float w = W[k * nout + n];
    __nv_bfloat16 h = __float2bfloat16_rn(w);
    float res = w - __bfloat162float(h);
    __nv_bfloat16 l = __float2bfloat16_rn(res);
    uint32_t off = phys(n, k);
    *reinterpret_cast<__nv_bfloat16*>(g_wimg + hoff + off)       = h;
    *reinterpret_cast<__nv_bfloat16*>(g_wimg + hoff + psz + off) = l;
}

// ---------------- fused 4-layer MLP on HMMA, BM=64, 2 CTAs/SM ---------------
#define SM_A_HI 0
#define SM_A_LO 16384
#define SM_W_HI 32768
#define SM_BIAS 98304
#define SM_TOTAL (98304 + 2048)     // 100352 bytes -> 2 CTAs/SM

template<int MT>
__device__ __forceinline__ void load_frags(
    uint32_t sb, uint32_t wlo, int kc,
    const uint32_t* arow_off, const int* ar7, int abit,
    const uint32_t* brow_off, const int* br7, int bbit,
    uint32_t ah[][4], uint32_t al[][4], uint32_t bh[][4], uint32_t bl[][4]) {
    #pragma unroll
    for (int mt = 0; mt < MT; mt++) {
        uint32_t off = arow_off[mt] + (uint32_t)((((kc << 1) + abit) ^ ar7[mt]) << 4);
        ldsm_x4(ah[mt], sb + SM_A_HI + off);
        ldsm_x4(al[mt], sb + SM_A_LO + off);
    }
    #pragma unroll
    for (int jp = 0; jp < 2; jp++) {
        uint32_t off = brow_off[jp] + (uint32_t)((((kc << 1) + bbit) ^ br7[jp]) << 4);
        ldsm_x4(bh[jp], sb + SM_W_HI + off);
        ldsm_x4(bl[jp], wlo + off);
    }
}

// Warp tile = 32 cols (NTILES=4, PAIRS=2).
// NOUT=128: warpM=wid>>2 (MT=2), warpN=wid&3; NOUT=64: warpM=wid>>1 (MT=1), warpN=wid&1.
template<int NOUT, bool LAST>
__device__ __forceinline__ void layer_body(char* smem, uint32_t sb, float* __restrict__ out,
                                           int wid, int lane, int m0, const float* bl_s,
                                           uint32_t next_hoff, int next_f4, int tid) {
    constexpr int MT = (NOUT == 128) ? 2 : 1;
    const uint32_t wlo = sb + SM_W_HI + (uint32_t)NOUT * 256u;

    int warpM = (NOUT == 128) ? (wid >> 2) : (wid >> 1);
    int warpN = (NOUT == 128) ? (wid & 3) : (wid & 1);
    int mi    = lane >> 3;
    int lane8 = lane & 7;
    int g     = lane >> 2;
    int tt    = lane & 3;
    int nbase = warpN * 32;

    uint32_t arow_off[MT]; int ar7[MT]; int abit = mi >> 1;
    #pragma unroll
    for (int mt = 0; mt < MT; mt++) {
        int row = warpM * (MT * 16) + mt * 16 + (mi & 1) * 8 + lane8;
        arow_off[mt] = (uint32_t)row * 256u;
        ar7[mt] = row & 7;
    }
    uint32_t brow_off[2]; int br7[2]; int bbit = mi & 1;
    #pragma unroll
    for (int jp = 0; jp < 2; jp++) {
        int row = nbase + jp * 16 + (mi >> 1) * 8 + lane8;
        brow_off[jp] = (uint32_t)row * 256u;
        br7[jp] = row & 7;
    }

    float acc[MT][4][4];
    #pragma unroll
    for (int mt = 0; mt < MT; mt++)
        #pragma unroll
        for (int j = 0; j < 4; j++)
            #pragma unroll
            for (int q = 0; q < 4; q++) acc[mt][j][q] = 0.f;

    // double-buffered fragments, explicit kc+1 prefetch
    uint32_t ah[2][MT][4], al[2][MT][4], bh[2][2][4], bl[2][2][4];
    load_frags<MT>(sb, wlo, 0, arow_off, ar7, abit, brow_off, br7, bbit,
                   ah[0], al[0], bh[0], bl[0]);
    #pragma unroll
    for (int kc = 0; kc < 8; kc++) {
        int cur = kc & 1;
        if (kc < 7)
            load_frags<MT>(sb, wlo, kc + 1, arow_off, ar7, abit, brow_off, br7, bbit,
                           ah[cur ^ 1], al[cur ^ 1], bh[cur ^ 1], bl[cur ^ 1]);
        // pass 1: ah*bh (all accs, independent)
        #pragma unroll
        for (int jp = 0; jp < 2; jp++)
            #pragma unroll
            for (int mt = 0; mt < MT; mt++) {
                mma_bf16(acc[mt][jp * 2],     ah[cur][mt], bh[cur][jp][0], bh[cur][jp][1]);
                mma_bf16(acc[mt][jp * 2 + 1], ah[cur][mt], bh[cur][jp][2], bh[cur][jp][3]);
            }
        // pass 2: ah*bl
        #pragma unroll
        for (int jp = 0; jp < 2; jp++)
            #pragma unroll
            for (int mt = 0; mt < MT; mt++) {
                mma_bf16(acc[mt][jp * 2],     ah[cur][mt], bl[cur][jp][0], bl[cur][jp][1]);
                mma_bf16(acc[mt][jp * 2 + 1], ah[cur][mt], bl[cur][jp][2], bl[cur][jp][3]);
            }
        // pass 3: al*bh
        #pragma unroll
        for (int jp = 0; jp < 2; jp++)
            #pragma unroll
            for (int mt = 0; mt < MT; mt++) {
                mma_bf16(acc[mt][jp * 2],     al[cur][mt], bh[cur][jp][0], bh[cur][jp][1]);
                mma_bf16(acc[mt][jp * 2 + 1], al[cur][mt], bh[cur][jp][2], bh[cur][jp][3]);
            }
    }
    __syncthreads();   // all A/W smem reads complete

    // prefetch next layer's weights under the epilogue
    if (!LAST) {
        const char* src = reinterpret_cast<const char*>(g_wimg + next_hoff);
        uint32_t dst = sb + SM_W_HI;
        for (int i = tid; i < next_f4; i += 256)
            cp16(dst + (uint32_t)i * 16u, src + (size_t)i * 16);
        CP_COMMIT();
    }

    #pragma unroll
    for (int mt = 0; mt < MT; mt++) {
        int rg0 = warpM * (MT * 16) + mt * 16 + g;
        #pragma unroll
        for (int j = 0; j < 4; j++) {
            int c0 = nbase + j * 8 + tt * 2;
            float bv0 = bl_s[c0], bv1 = bl_s[c0 + 1];
            float* d = acc[mt][j];
            if (!LAST) {
                float f0 = fmaxf(d[0] + bv0, 0.f), f1 = fmaxf(d[1] + bv1, 0.f);
                float f2 = fmaxf(d[2] + bv0, 0.f), f3 = fmaxf(d[3] + bv1, 0.f);
                __nv_bfloat16 h0 = __float2bfloat16_rn(f0), h1 = __float2bfloat16_rn(f1);
                __nv_bfloat16 h2 = __float2bfloat16_rn(f2), h3 = __float2bfloat16_rn(f3);
                uint32_t o0 = phys(rg0, c0);
                uint32_t o1 = phys(rg0 + 8, c0);
                *reinterpret_cast<uint32_t*>(smem + SM_A_HI + o0) =
                    bf2pack(__bfloat162float(h0), __bfloat162float(h1));
                *reinterpret_cast<uint32_t*>(smem + SM_A_LO + o0) =
                    bf2pack(f0 - __bfloat162float(h0), f1 - __bfloat162float(h1));
                *reinterpret_cast<uint32_t*>(smem + SM_A_HI + o1) =
                    bf2pack(__bfloat162float(h2), __bfloat162float(h3));
                *reinterpret_cast<uint32_t*>(smem + SM_A_LO + o1) =
                    bf2pack(f2 - __bfloat162float(h2), f3 - __bfloat162float(h3));
            } else {
                int node0 = m0 + rg0;
                int node1 = node0 + 8;
                if (node0 < N_NODES)
                    *reinterpret_cast<float2*>(out + (size_t)node0 * OUT_DIM + c0) =
                        make_float2(d[0] + bv0, d[1] + bv1);
                if (node1 < N_NODES)
                    *reinterpret_cast<float2*>(out + (size_t)node1 * OUT_DIM + c0) =
                        make_float2(d[2] + bv0, d[3] + bv1);
            }
        }
    }
    if (!LAST) CP_WAIT0();
    __syncthreads();
}

__global__ void __launch_bounds__(256, 2)
fused_mlp(const float* __restrict__ x,
          const float* __restrict__ b1, const float* __restrict__ b2,
          const float* __restrict__ b3, const float* __restrict__ b4,
          float* __restrict__ out) {
    extern __shared__ char smem[];
    uint32_t sb = smem_u32(smem);
    int tid = threadIdx.x, wid = tid >> 5, lane = tid & 31;
    int m0 = blockIdx.x * 64;

    float* bias_s = reinterpret_cast<float*>(smem + SM_BIAS);

    // layer-0 weights via cp.async, overlapping the A fill below
    {
        const char* src = reinterpret_cast<const char*>(g_wimg);
        uint32_t dst = sb + SM_W_HI;
        for (int i = tid; i < 4096; i += 256)
            cp16(dst + (uint32_t)i * 16u, src + (size_t)i * 16);
        CP_COMMIT();
    }

    // ---- A fill: 64 rows x (x | agg/deg); 4 threads per row ----
    {
        int row = tid >> 2;
        int sub = tid & 3;
        int node = m0 + row;
        int nsafe = node < N_NODES ? node : 0;
        float inv = 1.0f;
        const float4* src;
        if (sub < 2) src = reinterpret_cast<const float4*>(x) + (size_t)nsafe * 16;
        else {
            src = g_agg4 + (size_t)nsafe * 16;
            inv = 1.0f / fmaxf(g_deg[nsafe], 1.0f);
        }
        #pragma unroll
        for (int q = 0; q < 8; q++) {
            float4 v = make_float4(0.f, 0.f, 0.f, 0.f);
            if (node < N_NODES) v = src[(sub & 1) * 8 + q];
            if (sub >= 2) { v.x *= inv; v.y *= inv; v.z *= inv; v.w *= inv; }
            __nv_bfloat16 h0 = __float2bfloat16_rn(v.x), h1 = __float2bfloat16_rn(v.y);
            __nv_bfloat16 h2 = __float2bfloat16_rn(v.z), h3 = __float2bfloat16_rn(v.w);
            float r0 = v.x - __bfloat162float(h0), r1 = v.y - __bfloat162float(h1);
            float r2 = v.z - __bfloat162float(h2), r3 = v.w - __bfloat162float(h3);
            int c = sub * 32 + q * 4;
            uint32_t off = phys(row, c);
            ull hv = (ull)bf2pack(__bfloat162float(h0), __bfloat162float(h1))
                   | ((ull)bf2pack(__bfloat162float(h2), __bfloat162float(h3)) << 32);
            ull lv = (ull)bf2pack(r0, r1) | ((ull)bf2pack(r2, r3) << 32);
            *reinterpret_cast<ull*>(smem + SM_A_HI + off) = hv;
            *reinterpret_cast<ull*>(smem + SM_A_LO + off) = lv;
        }
        if (tid < 128) {
            bias_s[tid]       = b1[tid];
            bias_s[128 + tid] = b2[tid];
            bias_s[256 + tid] = b3[tid];
            bias_s[384 + tid] = (tid < 64) ? b4[tid] : 0.f;
        }
    }
    CP_WAIT0();
    __syncthreads();

    layer_body<128, false>(smem, sb, out, wid, lane, m0, bias_s,       65536, 4096, tid);
    layer_body<128, false>(smem, sb, out, wid, lane, m0, bias_s + 128, 131072, 4096, tid);
    layer_body<128, false>(smem, sb, out, wid, lane, m0, bias_s + 256, 196608, 2048, tid);
    layer_body<64,  true >(smem, sb, out, wid, lane, m0, bias_s + 384, 0, 0, tid);
}

// ---------------- launch ----------------------------------------------------
extern "C" void kernel_launch(void* const* d_in, const int* in_sizes, int n_in,
                              void* d_out, int out_size) {
    const float* x  = (const float*)d_in[0];
    const int*   ei = (const int*)  d_in[1];
    const float* W1 = (const float*)d_in[2];
    const float* b1 = (const float*)d_in[3];
    const float* W2 = (const float*)d_in[4];
    const float* b2 = (const float*)d_in[5];
    const float* W3 = (const float*)d_in[6];
    const float* b3 = (const float*)d_in[7];
    const float* W4 = (const float*)d_in[8];
    const float* b4 = (const float*)d_in[9];
    float* out = (float*)d_out;

    cudaFuncSetAttribute(fused_mlp, cudaFuncAttributeMaxDynamicSharedMemorySize, SM_TOTAL);

    {
        int n4 = (N_NODES * IN_DIM) / 4;
        zero_kernel<<<(n4 + 255) / 256, 256>>>();
    }
    {
        long long threads = (long long)N_EDGES * 8;
        scatter_kernel<<<(int)((threads + 255) / 256), 256>>>(x, ei);
    }
    prep_weights<<<(57344 + 255) / 256, 256>>>(W1, W2, W3, W4);
    int gblocks = (N_NODES + 63) / 64;   // 1563
    fused_mlp<<<gblocks, 256, SM_TOTAL>>>(x, b1, b2, b3, b4, out);
}

// round 12
// speedup vs baseline: 2.9682x; 1.1954x over previous
#include <cuda_runtime.h>
#include <cuda_bf16.h>
#include <cstdint>

#define N_NODES 100000
#define N_EDGES 1250000
#define IN_DIM  64
#define HID     128
#define OUT_DIM 64
#define NB      ((N_NODES + 255) / 256)   // 391 scan blocks

typedef unsigned long long ull;

// ---------------- scratch ---------------------------------------------------
__device__ float4 g_agg4[(size_t)N_NODES * IN_DIM / 4];   // mean-aggregated feats
__device__ int    g_deg   [N_NODES];
__device__ int    g_start [N_NODES];
__device__ int    g_cursor[N_NODES];
__device__ int    g_bcol  [N_EDGES];
__device__ int    g_bsum  [NB];
__device__ int    g_boff  [NB];
// weight image: per layer [n][k] hi/lo bf16 planes, 256B rows, XOR swizzle
__device__ __align__(16) unsigned char g_wimg[229376];

// ---------------- helpers ---------------------------------------------------
__device__ __forceinline__ uint32_t smem_u32(const void* p) {
    uint32_t a;
    asm("{ .reg .u64 t; cvta.to.shared.u64 t, %1; cvt.u32.u64 %0, t; }" : "=r"(a) : "l"(p));
    return a;
}
__device__ __forceinline__ uint32_t phys(int row, int col) {
    return (uint32_t)row * 256u
         + (uint32_t)(((col >> 3) ^ (row & 7)) << 4)
         + (uint32_t)((col & 7) << 1);
}
__device__ __forceinline__ uint32_t bf2pack(float f0, float f1) {
    __nv_bfloat162 t = __floats2bfloat162_rn(f0, f1);
    return *reinterpret_cast<uint32_t*>(&t);
}
__device__ __forceinline__ void ldsm_x4(uint32_t* r, uint32_t addr) {
    asm volatile("ldmatrix.sync.aligned.m8n8.x4.shared.b16 {%0,%1,%2,%3}, [%4];"
                 : "=r"(r[0]), "=r"(r[1]), "=r"(r[2]), "=r"(r[3]) : "r"(addr));
}
__device__ __forceinline__ void mma_bf16(float* d, const uint32_t* a, uint32_t b0, uint32_t b1) {
    asm volatile(
        "mma.sync.aligned.m16n8k16.row.col.f32.bf16.bf16.f32 "
        "{%0,%1,%2,%3}, {%4,%5,%6,%7}, {%8,%9}, {%0,%1,%2,%3};"
        : "+f"(d[0]), "+f"(d[1]), "+f"(d[2]), "+f"(d[3])
        : "r"(a[0]), "r"(a[1]), "r"(a[2]), "r"(a[3]), "r"(b0), "r"(b1));
}
__device__ __forceinline__ void cp16(uint32_t dst, const void* src) {
    asm volatile("cp.async.cg.shared.global [%0], [%1], 16;" :: "r"(dst), "l"(src));
}
#define CP_COMMIT() asm volatile("cp.async.commit_group;" ::: "memory")
#define CP_WAIT0()  asm volatile("cp.async.wait_group 0;" ::: "memory")

// ================= CSR aggregation pipeline =================================
__global__ void zero_deg() {
    int i = blockIdx.x * blockDim.x + threadIdx.x;
    if (i < N_NODES) g_deg[i] = 0;
}
__global__ void hist_kernel(const int* __restrict__ ei) {
    int t = blockIdx.x * blockDim.x + threadIdx.x;
    if (t < N_EDGES) atomicAdd(&g_deg[ei[t]], 1);
}
// block sums of deg (256 per block)
__global__ void scan1() {
    __shared__ int s[256];
    int tid = threadIdx.x;
    int i = blockIdx.x * 256 + tid;
    s[tid] = (i < N_NODES) ? g_deg[i] : 0;
    __syncthreads();
    #pragma unroll
    for (int d = 128; d > 0; d >>= 1) {
        if (tid < d) s[tid] += s[tid + d];
        __syncthreads();
    }
    if (tid == 0) g_bsum[blockIdx.x] = s[0];
}
// single-block exclusive scan over NB block sums
__global__ void scan2() {
    __shared__ int s[512];
    int tid = threadIdx.x;
    int v = (tid < NB) ? g_bsum[tid] : 0;
    s[tid] = v;
    __syncthreads();
    #pragma unroll
    for (int d = 1; d < 512; d <<= 1) {
        int t = (tid >= d) ? s[tid - d] : 0;
        __syncthreads();
        s[tid] += t;
        __syncthreads();
    }
    if (tid < NB) g_boff[tid] = s[tid] - v;   // exclusive
}
// per-block exclusive rescan + block offset -> start, cursor
__global__ void scan3() {
    __shared__ int s[256];
    int tid = threadIdx.x;
    int i = blockIdx.x * 256 + tid;
    int v = (i < N_NODES) ? g_deg[i] : 0;
    s[tid] = v;
    __syncthreads();
    #pragma unroll
    for (int d = 1; d < 256; d <<= 1) {
        int t = (tid >= d) ? s[tid - d] : 0;
        __syncthreads();
        s[tid] += t;
        __syncthreads();
    }
    if (i < N_NODES) {
        int start = g_boff[blockIdx.x] + s[tid] - v;
        g_start[i]  = start;
        g_cursor[i] = start;
    }
}
__global__ void bin_kernel(const int* __restrict__ ei) {
    int t = blockIdx.x * blockDim.x + threadIdx.x;
    if (t >= N_EDGES) return;
    int row = ei[t];
    int col = ei[N_EDGES + t];
    int pos = atomicAdd(&g_cursor[row], 1);
    g_bcol[pos] = col;
}
// 16 threads per node: accumulate neighbor float4s in registers, store mean.
__global__ void gather_kernel(const float* __restrict__ x) {
    int gt = blockIdx.x * blockDim.x + threadIdx.x;
    int node = gt >> 4;
    if (node >= N_NODES) return;
    int q = gt & 15;
    int start = g_start[node];
    int end   = g_cursor[node];          // == start + deg after bin
    float4 acc = make_float4(0.f, 0.f, 0.f, 0.f);
    int i = start;
    for (; i + 1 < end; i += 2) {
        int c0 = g_bcol[i], c1 = g_bcol[i + 1];
        float4 v0 = reinterpret_cast<const float4*>(x)[(size_t)c0 * 16 + q];
        float4 v1 = reinterpret_cast<const float4*>(x)[(size_t)c1 * 16 + q];
        acc.x += v0.x + v1.x; acc.y += v0.y + v1.y;
        acc.z += v0.z + v1.z; acc.w += v0.w + v1.w;
    }
    if (i < end) {
        int c = g_bcol[i];
        float4 v = reinterpret_cast<const float4*>(x)[(size_t)c * 16 + q];
        acc.x += v.x; acc.y += v.y; acc.z += v.z; acc.w += v.w;
    }
    int d = end - start;
    float inv = 1.0f / (float)(d > 0 ? d : 1);
    acc.x *= inv; acc.y *= inv; acc.z *= inv; acc.w *= inv;
    g_agg4[(size_t)node * 16 + q] = acc;
}

// ---------------- weight prep -----------------------------------------------
__global__ void prep_weights(const float* __restrict__ W1, const float* __restrict__ W2,
                             const float* __restrict__ W3, const float* __restrict__ W4) {
    int t = blockIdx.x * blockDim.x + threadIdx.x;
    if (t >= 57344) return;
    const float* W; int e, nout; uint32_t hoff, psz;
    if      (t < 16384) { e = t;         W = W1; nout = 128; hoff = 0;      psz = 32768; }
    else if (t < 32768) { e = t - 16384; W = W2; nout = 128; hoff = 65536;  psz = 32768; }
    else if (t < 49152) { e = t - 32768; W = W3; nout = 128; hoff = 131072; psz = 32768; }
    else                { e = t - 49152; W = W4; nout = 64;  hoff = 196608; psz = 16384; }
    int n = e >> 7;
    int k = e & 127;
    float w = W[k * nout + n];
    __nv_bfloat16 h = __float2bfloat16_rn(w);
    float res = w - __bfloat162float(h);
    __nv_bfloat16 l = __float2bfloat16_rn(res);
    uint32_t off = phys(n, k);
    *reinterpret_cast<__nv_bfloat16*>(g_wimg + hoff + off)       = h;
    *reinterpret_cast<__nv_bfloat16*>(g_wimg + hoff + psz + off) = l;
}

// ---------------- fused 4-layer MLP on HMMA, BM=64, 2 CTAs/SM ---------------
#define SM_A_HI 0
#define SM_A_LO 16384
#define SM_W_HI 32768
#define SM_BIAS 98304
#define SM_TOTAL (98304 + 2048)     // 100352 bytes -> 2 CTAs/SM

template<int MT>
__device__ __forceinline__ void load_frags(
    uint32_t sb, uint32_t wlo, int kc,
    const uint32_t* arow_off, const int* ar7, int abit,
    const uint32_t* brow_off, const int* br7, int bbit,
    uint32_t ah[][4], uint32_t al[][4], uint32_t bh[][4], uint32_t bl[][4]) {
    #pragma unroll
    for (int mt = 0; mt < MT; mt++) {
        uint32_t off = arow_off[mt] + (uint32_t)((((kc << 1) + abit) ^ ar7[mt]) << 4);
        ldsm_x4(ah[mt], sb + SM_A_HI + off);
        ldsm_x4(al[mt], sb + SM_A_LO + off);
    }
    #pragma unroll
    for (int jp = 0; jp < 2; jp++) {
        uint32_t off = brow_off[jp] + (uint32_t)((((kc << 1) + bbit) ^ br7[jp]) << 4);
        ldsm_x4(bh[jp], sb + SM_W_HI + off);
        ldsm_x4(bl[jp], wlo + off);
    }
}

template<int NOUT, bool LAST>
__device__ __forceinline__ void layer_body(char* smem, uint32_t sb, float* __restrict__ out,
                                           int wid, int lane, int m0, const float* bl_s,
                                           uint32_t next_hoff, int next_f4, int tid) {
    constexpr int MT = (NOUT == 128) ? 2 : 1;
    const uint32_t wlo = sb + SM_W_HI + (uint32_t)NOUT * 256u;

    int warpM = (NOUT == 128) ? (wid >> 2) : (wid >> 1);
    int warpN = (NOUT == 128) ? (wid & 3) : (wid & 1);
    int mi    = lane >> 3;
    int lane8 = lane & 7;
    int g     = lane >> 2;
    int tt    = lane & 3;
    int nbase = warpN * 32;

    uint32_t arow_off[MT]; int ar7[MT]; int abit = mi >> 1;
    #pragma unroll
    for (int mt = 0; mt < MT; mt++) {
        int row = warpM * (MT * 16) + mt * 16 + (mi & 1) * 8 + lane8;
        arow_off[mt] = (uint32_t)row * 256u;
        ar7[mt] = row & 7;
    }
    uint32_t brow_off[2]; int br7[2]; int bbit = mi & 1;
    #pragma unroll
    for (int jp = 0; jp < 2; jp++) {
        int row = nbase + jp * 16 + (mi >> 1) * 8 + lane8;
        brow_off[jp] = (uint32_t)row * 256u;
        br7[jp] = row & 7;
    }

    float acc[MT][4][4];
    #pragma unroll
    for (int mt = 0; mt < MT; mt++)
        #pragma unroll
        for (int j = 0; j < 4; j++)
            #pragma unroll
            for (int q = 0; q < 4; q++) acc[mt][j][q] = 0.f;

    uint32_t ah[2][MT][4], al[2][MT][4], bh[2][2][4], bl[2][2][4];
    load_frags<MT>(sb, wlo, 0, arow_off, ar7, abit, brow_off, br7, bbit,
                   ah[0], al[0], bh[0], bl[0]);
    #pragma unroll
    for (int kc = 0; kc < 8; kc++) {
        int cur = kc & 1;
        if (kc < 7)
            load_frags<MT>(sb, wlo, kc + 1, arow_off, ar7, abit, brow_off, br7, bbit,
                           ah[cur ^ 1], al[cur ^ 1], bh[cur ^ 1], bl[cur ^ 1]);
        #pragma unroll
        for (int jp = 0; jp < 2; jp++)
            #pragma unroll
            for (int mt = 0; mt < MT; mt++) {
                mma_bf16(acc[mt][jp * 2],     ah[cur][mt], bh[cur][jp][0], bh[cur][jp][1]);
                mma_bf16(acc[mt][jp * 2 + 1], ah[cur][mt], bh[cur][jp][2], bh[cur][jp][3]);
            }
        #pragma unroll
        for (int jp = 0; jp < 2; jp++)
            #pragma unroll
            for (int mt = 0; mt < MT; mt++) {
                mma_bf16(acc[mt][jp * 2],     ah[cur][mt], bl[cur][jp][0], bl[cur][jp][1]);
                mma_bf16(acc[mt][jp * 2 + 1], ah[cur][mt], bl[cur][jp][2], bl[cur][jp][3]);
            }
        #pragma unroll
        for (int jp = 0; jp < 2; jp++)
            #pragma unroll
            for (int mt = 0; mt < MT; mt++) {
                mma_bf16(acc[mt][jp * 2],     al[cur][mt], bh[cur][jp][0], bh[cur][jp][1]);
                mma_bf16(acc[mt][jp * 2 + 1], al[cur][mt], bh[cur][jp][2], bh[cur][jp][3]);
            }
    }
    __syncthreads();

    if (!LAST) {
        const char* src = reinterpret_cast<const char*>(g_wimg + next_hoff);
        uint32_t dst = sb + SM_W_HI;
        for (int i = tid; i < next_f4; i += 256)
            cp16(dst + (uint32_t)i * 16u, src + (size_t)i * 16);
        CP_COMMIT();
    }

    #pragma unroll
    for (int mt = 0; mt < MT; mt++) {
        int rg0 = warpM * (MT * 16) + mt * 16 + g;
        #pragma unroll
        for (int j = 0; j < 4; j++) {
            int c0 = nbase + j * 8 + tt * 2;
            float bv0 = bl_s[c0], bv1 = bl_s[c0 + 1];
            float* d = acc[mt][j];
            if (!LAST) {
                float f0 = fmaxf(d[0] + bv0, 0.f), f1 = fmaxf(d[1] + bv1, 0.f);
                float f2 = fmaxf(d[2] + bv0, 0.f), f3 = fmaxf(d[3] + bv1, 0.f);
                __nv_bfloat16 h0 = __float2bfloat16_rn(f0), h1 = __float2bfloat16_rn(f1);
                __nv_bfloat16 h2 = __float2bfloat16_rn(f2), h3 = __float2bfloat16_rn(f3);
                uint32_t o0 = phys(rg0, c0);
                uint32_t o1 = phys(rg0 + 8, c0);
                *reinterpret_cast<uint32_t*>(smem + SM_A_HI + o0) =
                    bf2pack(__bfloat162float(h0), __bfloat162float(h1));
                *reinterpret_cast<uint32_t*>(smem + SM_A_LO + o0) =
                    bf2pack(f0 - __bfloat162float(h0), f1 - __bfloat162float(h1));
                *reinterpret_cast<uint32_t*>(smem + SM_A_HI + o1) =
                    bf2pack(__bfloat162float(h2), __bfloat162float(h3));
                *reinterpret_cast<uint32_t*>(smem + SM_A_LO + o1) =
                    bf2pack(f2 - __bfloat162float(h2), f3 - __bfloat162float(h3));
            } else {
                int node0 = m0 + rg0;
                int node1 = node0 + 8;
                if (node0 < N_NODES)
                    *reinterpret_cast<float2*>(out + (size_t)node0 * OUT_DIM + c0) =
                        make_float2(d[0] + bv0, d[1] + bv1);
                if (node1 < N_NODES)
                    *reinterpret_cast<float2*>(out + (size_t)node1 * OUT_DIM + c0) =
                        make_float2(d[2] + bv0, d[3] + bv1);
            }
        }
    }
    if (!LAST) CP_WAIT0();
    __syncthreads();
}

__global__ void __launch_bounds__(256, 2)
fused_mlp(const float* __restrict__ x,
          const float* __restrict__ b1, const float* __restrict__ b2,
          const float* __restrict__ b3, const float* __restrict__ b4,
          float* __restrict__ out) {
    extern __shared__ char smem[];
    uint32_t sb = smem_u32(smem);
    int tid = threadIdx.x, wid = tid >> 5, lane = tid & 31;
    int m0 = blockIdx.x * 64;

    float* bias_s = reinterpret_cast<float*>(smem + SM_BIAS);

    // layer-0 weights via cp.async, overlapping the A fill
    {
        const char* src = reinterpret_cast<const char*>(g_wimg);
        uint32_t dst = sb + SM_W_HI;
        for (int i = tid; i < 4096; i += 256)
            cp16(dst + (uint32_t)i * 16u, src + (size_t)i * 16);
        CP_COMMIT();
    }

    // ---- A fill: 64 rows x (x | agg-mean); 4 threads per row ----
    {
        int row = tid >> 2;
        int sub = tid & 3;
        int node = m0 + row;
        int nsafe = node < N_NODES ? node : 0;
        const float4* src = (sub < 2)
            ? reinterpret_cast<const float4*>(x) + (size_t)nsafe * 16
            : g_agg4 + (size_t)nsafe * 16;
        #pragma unroll
        for (int q = 0; q < 8; q++) {
            float4 v = make_float4(0.f, 0.f, 0.f, 0.f);
            if (node < N_NODES) v = src[(sub & 1) * 8 + q];
            __nv_bfloat16 h0 = __float2bfloat16_rn(v.x), h1 = __float2bfloat16_rn(v.y);
            __nv_bfloat16 h2 = __float2bfloat16_rn(v.z), h3 = __float2bfloat16_rn(v.w);
            float r0 = v.x - __bfloat162float(h0), r1 = v.y - __bfloat162float(h1);
            float r2 = v.z - __bfloat162float(h2), r3 = v.w - __bfloat162float(h3);
            int c = sub * 32 + q * 4;
            uint32_t off = phys(row, c);
            ull hv = (ull)bf2pack(__bfloat162float(h0), __bfloat162float(h1))
                   | ((ull)bf2pack(__bfloat162float(h2), __bfloat162float(h3)) << 32);
            ull lv = (ull)bf2pack(r0, r1) | ((ull)bf2pack(r2, r3) << 32);
            *reinterpret_cast<ull*>(smem + SM_A_HI + off) = hv;
            *reinterpret_cast<ull*>(smem + SM_A_LO + off) = lv;
        }
        if (tid < 128) {
            bias_s[tid]       = b1[tid];
            bias_s[128 + tid] = b2[tid];
            bias_s[256 + tid] = b3[tid];
            bias_s[384 + tid] = (tid < 64) ? b4[tid] : 0.f;
        }
    }
    CP_WAIT0();
    __syncthreads();

    layer_body<128, false>(smem, sb, out, wid, lane, m0, bias_s,       65536, 4096, tid);
    layer_body<128, false>(smem, sb, out, wid, lane, m0, bias_s + 128, 131072, 4096, tid);
    layer_body<128, false>(smem, sb, out, wid, lane, m0, bias_s + 256, 196608, 2048, tid);
    layer_body<64,  true >(smem, sb, out, wid, lane, m0, bias_s + 384, 0, 0, tid);
}

// ---------------- launch ----------------------------------------------------
extern "C" void kernel_launch(void* const* d_in, const int* in_sizes, int n_in,
                              void* d_out, int out_size) {
    const float* x  = (const float*)d_in[0];
    const int*   ei = (const int*)  d_in[1];
    const float* W1 = (const float*)d_in[2];
    const float* b1 = (const float*)d_in[3];
    const float* W2 = (const float*)d_in[4];
    const float* b2 = (const float*)d_in[5];
    const float* W3 = (const float*)d_in[6];
    const float* b3 = (const float*)d_in[7];
    const float* W4 = (const float*)d_in[8];
    const float* b4 = (const float*)d_in[9];
    float* out = (float*)d_out;

    cudaFuncSetAttribute(fused_mlp, cudaFuncAttributeMaxDynamicSharedMemorySize, SM_TOTAL);

    // CSR aggregation
    zero_deg<<<NB, 256>>>();
    hist_kernel<<<(N_EDGES + 255) / 256, 256>>>(ei);
    scan1<<<NB, 256>>>();
    scan2<<<1, 512>>>();
    scan3<<<NB, 256>>>();
    bin_kernel<<<(N_EDGES + 255) / 256, 256>>>(ei);
    gather_kernel<<<(N_NODES * 16 + 255) / 256, 256>>>(x);
    // weights + MLP
    prep_weights<<<(57344 + 255) / 256, 256>>>(W1, W2, W3, W4);
    int gblocks = (N_NODES + 63) / 64;   // 1563
    fused_mlp<<<gblocks, 256, SM_TOTAL>>>(x, b1, b2, b3, b4, out);
}

// round 13
// speedup vs baseline: 3.0329x; 1.0218x over previous
#include <cuda_runtime.h>
#include <cuda_bf16.h>
#include <cstdint>

#define N_NODES 100000
#define N_EDGES 1250000
#define IN_DIM  64
#define HID     128
#define OUT_DIM 64
#define NB      ((N_NODES + 255) / 256)   // 391 blocks

typedef unsigned long long ull;

// ---------------- scratch ---------------------------------------------------
__device__ int    g_deg   [N_NODES];
__device__ int    g_start [N_NODES];
__device__ int    g_cursor[N_NODES];
__device__ int    g_bcol  [N_EDGES];
__device__ int    g_total;
// weight image: per layer [n][k] hi/lo bf16 planes, 256B rows, XOR swizzle
__device__ __align__(16) unsigned char g_wimg[229376];

// ---------------- helpers ---------------------------------------------------
__device__ __forceinline__ uint32_t smem_u32(const void* p) {
    uint32_t a;
    asm("{ .reg .u64 t; cvta.to.shared.u64 t, %1; cvt.u32.u64 %0, t; }" : "=r"(a) : "l"(p));
    return a;
}
__device__ __forceinline__ uint32_t phys(int row, int col) {
    return (uint32_t)row * 256u
         + (uint32_t)(((col >> 3) ^ (row & 7)) << 4)
         + (uint32_t)((col & 7) << 1);
}
__device__ __forceinline__ uint32_t bf2pack(float f0, float f1) {
    __nv_bfloat162 t = __floats2bfloat162_rn(f0, f1);
    return *reinterpret_cast<uint32_t*>(&t);
}
__device__ __forceinline__ void ldsm_x4(uint32_t* r, uint32_t addr) {
    asm volatile("ldmatrix.sync.aligned.m8n8.x4.shared.b16 {%0,%1,%2,%3}, [%4];"
                 : "=r"(r[0]), "=r"(r[1]), "=r"(r[2]), "=r"(r[3]) : "r"(addr));
}
__device__ __forceinline__ void mma_bf16(float* d, const uint32_t* a, uint32_t b0, uint32_t b1) {
    asm volatile(
        "mma.sync.aligned.m16n8k16.row.col.f32.bf16.bf16.f32 "
        "{%0,%1,%2,%3}, {%4,%5,%6,%7}, {%8,%9}, {%0,%1,%2,%3};"
        : "+f"(d[0]), "+f"(d[1]), "+f"(d[2]), "+f"(d[3])
        : "r"(a[0]), "r"(a[1]), "r"(a[2]), "r"(a[3]), "r"(b0), "r"(b1));
}
__device__ __forceinline__ void cp16(uint32_t dst, const void* src) {
    asm volatile("cp.async.cg.shared.global [%0], [%1], 16;" :: "r"(dst), "l"(src));
}
#define CP_COMMIT() asm volatile("cp.async.commit_group;" ::: "memory")
#define CP_WAIT0()  asm volatile("cp.async.wait_group 0;" ::: "memory")

// ================= CSR build =================================================
__global__ void zero_deg() {
    int i = blockIdx.x * blockDim.x + threadIdx.x;
    if (i < N_NODES) g_deg[i] = 0;
    if (i == 0) g_total = 0;
}
__global__ void hist_kernel(const int* __restrict__ ei) {
    int t = blockIdx.x * blockDim.x + threadIdx.x;
    if (t < N_EDGES) atomicAdd(&g_deg[ei[t]], 1);
}
// one-shot alloc: block inclusive scan + atomic global base
__global__ void alloc_kernel() {
    __shared__ int s[256];
    __shared__ int base;
    int tid = threadIdx.x;
    int i = blockIdx.x * 256 + tid;
    int v = (i < N_NODES) ? g_deg[i] : 0;
    s[tid] = v;
    __syncthreads();
    #pragma unroll
    for (int d = 1; d < 256; d <<= 1) {
        int t = (tid >= d) ? s[tid - d] : 0;
        __syncthreads();
        s[tid] += t;
        __syncthreads();
    }
    if (tid == 255) base = atomicAdd(&g_total, s[255]);
    __syncthreads();
    if (i < N_NODES) {
        int start = base + s[tid] - v;
        g_start[i]  = start;
        g_cursor[i] = start;
    }
}
__global__ void bin_kernel(const int* __restrict__ ei) {
    int t = blockIdx.x * blockDim.x + threadIdx.x;
    if (t >= N_EDGES) return;
    int row = ei[t];
    int col = ei[N_EDGES + t];
    int pos = atomicAdd(&g_cursor[row], 1);
    g_bcol[pos] = col;
}

// ---------------- weight prep -----------------------------------------------
__global__ void prep_weights(const float* __restrict__ W1, const float* __restrict__ W2,
                             const float* __restrict__ W3, const float* __restrict__ W4) {
    int t = blockIdx.x * blockDim.x + threadIdx.x;
    if (t >= 57344) return;
    const float* W; int e, nout; uint32_t hoff, psz;
    if      (t < 16384) { e = t;         W = W1; nout = 128; hoff = 0;      psz = 32768; }
    else if (t < 32768) { e = t - 16384; W = W2; nout = 128; hoff = 65536;  psz = 32768; }
    else if (t < 49152) { e = t - 32768; W = W3; nout = 128; hoff = 131072; psz = 32768; }
    else                { e = t - 49152; W = W4; nout = 64;  hoff = 196608; psz = 16384; }
    int n = e >> 7;
    int k = e & 127;
    float w = W[k * nout + n];
    __nv_bfloat16 h = __float2bfloat16_rn(w);
    float res = w - __bfloat162float(h);
    __nv_bfloat16 l = __float2bfloat16_rn(res);
    uint32_t off = phys(n, k);
    *reinterpret_cast<__nv_bfloat16*>(g_wimg + hoff + off)       = h;
    *reinterpret_cast<__nv_bfloat16*>(g_wimg + hoff + psz + off) = l;
}

// ---------------- fused gather + 4-layer MLP on HMMA ------------------------
#define SM_A_HI 0
#define SM_A_LO 16384
#define SM_W_HI 32768
#define SM_BIAS 98304
#define SM_TOTAL (98304 + 2048)     // 100352 bytes -> 2 CTAs/SM

template<int MT>
__device__ __forceinline__ void load_frags(
    uint32_t sb, uint32_t wlo, int kc,
    const uint32_t* arow_off, const int* ar7, int abit,
    const uint32_t* brow_off, const int* br7, int bbit,
    uint32_t ah[][4], uint32_t al[][4], uint32_t bh[][4], uint32_t bl[][4]) {
    #pragma unroll
    for (int mt = 0; mt < MT; mt++) {
        uint32_t off = arow_off[mt] + (uint32_t)((((kc << 1) + abit) ^ ar7[mt]) << 4);
        ldsm_x4(ah[mt], sb + SM_A_HI + off);
        ldsm_x4(al[mt], sb + SM_A_LO + off);
    }
    #pragma unroll
    for (int jp = 0; jp < 2; jp++) {
        uint32_t off = brow_off[jp] + (uint32_t)((((kc << 1) + bbit) ^ br7[jp]) << 4);
        ldsm_x4(bh[jp], sb + SM_W_HI + off);
        ldsm_x4(bl[jp], wlo + off);
    }
}

template<int NOUT, bool LAST>
__device__ __forceinline__ void layer_body(char* smem, uint32_t sb, float* __restrict__ out,
                                           int wid, int lane, int m0, const float* bl_s,
                                           uint32_t next_hoff, int next_f4, int tid) {
    constexpr int MT = (NOUT == 128) ? 2 : 1;
    const uint32_t wlo = sb + SM_W_HI + (uint32_t)NOUT * 256u;

    int warpM = (NOUT == 128) ? (wid >> 2) : (wid >> 1);
    int warpN = (NOUT == 128) ? (wid & 3) : (wid & 1);
    int mi    = lane >> 3;
    int lane8 = lane & 7;
    int g     = lane >> 2;
    int tt    = lane & 3;
    int nbase = warpN * 32;

    uint32_t arow_off[MT]; int ar7[MT]; int abit = mi >> 1;
    #pragma unroll
    for (int mt = 0; mt < MT; mt++) {
        int row = warpM * (MT * 16) + mt * 16 + (mi & 1) * 8 + lane8;
        arow_off[mt] = (uint32_t)row * 256u;
        ar7[mt] = row & 7;
    }
    uint32_t brow_off[2]; int br7[2]; int bbit = mi & 1;
    #pragma unroll
    for (int jp = 0; jp < 2; jp++) {
        int row = nbase + jp * 16 + (mi >> 1) * 8 + lane8;
        brow_off[jp] = (uint32_t)row * 256u;
        br7[jp] = row & 7;
    }

    float acc[MT][4][4];
    #pragma unroll
    for (int mt = 0; mt < MT; mt++)
        #pragma unroll
        for (int j = 0; j < 4; j++)
            #pragma unroll
            for (int q = 0; q < 4; q++) acc[mt][j][q] = 0.f;

    uint32_t ah[2][MT][4], al[2][MT][4], bh[2][2][4], bl[2][2][4];
    load_frags<MT>(sb, wlo, 0, arow_off, ar7, abit, brow_off, br7, bbit,
                   ah[0], al[0], bh[0], bl[0]);
    #pragma unroll
    for (int kc = 0; kc < 8; kc++) {
        int cur = kc & 1;
        if (kc < 7)
            load_frags<MT>(sb, wlo, kc + 1, arow_off, ar7, abit, brow_off, br7, bbit,
                           ah[cur ^ 1], al[cur ^ 1], bh[cur ^ 1], bl[cur ^ 1]);
        #pragma unroll
        for (int jp = 0; jp < 2; jp++)
            #pragma unroll
            for (int mt = 0; mt < MT; mt++) {
                mma_bf16(acc[mt][jp * 2],     ah[cur][mt], bh[cur][jp][0], bh[cur][jp][1]);
                mma_bf16(acc[mt][jp * 2 + 1], ah[cur][mt], bh[cur][jp][2], bh[cur][jp][3]);
            }
        #pragma unroll
        for (int jp = 0; jp < 2; jp++)
            #pragma unroll
            for (int mt = 0; mt < MT; mt++) {
                mma_bf16(acc[mt][jp * 2],     ah[cur][mt], bl[cur][jp][0], bl[cur][jp][1]);
                mma_bf16(acc[mt][jp * 2 + 1], ah[cur][mt], bl[cur][jp][2], bl[cur][jp][3]);
            }
        #pragma unroll
        for (int jp = 0; jp < 2; jp++)
            #pragma unroll
            for (int mt = 0; mt < MT; mt++) {
                mma_bf16(acc[mt][jp * 2],     al[cur][mt], bh[cur][jp][0], bh[cur][jp][1]);
                mma_bf16(acc[mt][jp * 2 + 1], al[cur][mt], bh[cur][jp][2], bh[cur][jp][3]);
            }
    }
    __syncthreads();

    if (!LAST) {
        const char* src = reinterpret_cast<const char*>(g_wimg + next_hoff);
        uint32_t dst = sb + SM_W_HI;
        for (int i = tid; i < next_f4; i += 256)
            cp16(dst + (uint32_t)i * 16u, src + (size_t)i * 16);
        CP_COMMIT();
    }

    #pragma unroll
    for (int mt = 0; mt < MT; mt++) {
        int rg0 = warpM * (MT * 16) + mt * 16 + g;
        #pragma unroll
        for (int j = 0; j < 4; j++) {
            int c0 = nbase + j * 8 + tt * 2;
            float bv0 = bl_s[c0], bv1 = bl_s[c0 + 1];
            float* d = acc[mt][j];
            if (!LAST) {
                float f0 = fmaxf(d[0] + bv0, 0.f), f1 = fmaxf(d[1] + bv1, 0.f);
                float f2 = fmaxf(d[2] + bv0, 0.f), f3 = fmaxf(d[3] + bv1, 0.f);
                __nv_bfloat16 h0 = __float2bfloat16_rn(f0), h1 = __float2bfloat16_rn(f1);
                __nv_bfloat16 h2 = __float2bfloat16_rn(f2), h3 = __float2bfloat16_rn(f3);
                uint32_t o0 = phys(rg0, c0);
                uint32_t o1 = phys(rg0 + 8, c0);
                *reinterpret_cast<uint32_t*>(smem + SM_A_HI + o0) =
                    bf2pack(__bfloat162float(h0), __bfloat162float(h1));
                *reinterpret_cast<uint32_t*>(smem + SM_A_LO + o0) =
                    bf2pack(f0 - __bfloat162float(h0), f1 - __bfloat162float(h1));
                *reinterpret_cast<uint32_t*>(smem + SM_A_HI + o1) =
                    bf2pack(__bfloat162float(h2), __bfloat162float(h3));
                *reinterpret_cast<uint32_t*>(smem + SM_A_LO + o1) =
                    bf2pack(f2 - __bfloat162float(h2), f3 - __bfloat162float(h3));
            } else {
                int node0 = m0 + rg0;
                int node1 = node0 + 8;
                if (node0 < N_NODES)
                    *reinterpret_cast<float2*>(out + (size_t)node0 * OUT_DIM + c0) =
                        make_float2(d[0] + bv0, d[1] + bv1);
                if (node1 < N_NODES)
                    *reinterpret_cast<float2*>(out + (size_t)node1 * OUT_DIM + c0) =
                        make_float2(d[2] + bv0, d[3] + bv1);
            }
        }
    }
    if (!LAST) CP_WAIT0();
    __syncthreads();
}

__global__ void __launch_bounds__(256, 2)
fused_mlp(const float* __restrict__ x,
          const float* __restrict__ b1, const float* __restrict__ b2,
          const float* __restrict__ b3, const float* __restrict__ b4,
          float* __restrict__ out) {
    extern __shared__ char smem[];
    uint32_t sb = smem_u32(smem);
    int tid = threadIdx.x, wid = tid >> 5, lane = tid & 31;
    int m0 = blockIdx.x * 64;

    float* bias_s = reinterpret_cast<float*>(smem + SM_BIAS);

    // layer-0 weights via cp.async, overlapping gather + A fill
    {
        const char* src = reinterpret_cast<const char*>(g_wimg);
        uint32_t dst = sb + SM_W_HI;
        for (int i = tid; i < 4096; i += 256)
            cp16(dst + (uint32_t)i * 16u, src + (size_t)i * 16);
        CP_COMMIT();
    }

    // ---- A fill with in-kernel CSR gather: 4 threads per row ----
    {
        int row = tid >> 2;
        int sub = tid & 3;                 // 4 float4-columns each
        int node = m0 + row;
        int nsafe = node < N_NODES ? node : 0;

        // x half: this thread's 4 float4 (cols sub*16 .. sub*16+15)
        const float4* xs = reinterpret_cast<const float4*>(x) + (size_t)nsafe * 16 + sub * 4;
        float4 xv[4];
        #pragma unroll
        for (int i = 0; i < 4; i++)
            xv[i] = (node < N_NODES) ? xs[i] : make_float4(0.f, 0.f, 0.f, 0.f);

        // agg half: gather-mean over CSR edge list, same 4 float4 columns
        float4 acc[4];
        #pragma unroll
        for (int i = 0; i < 4; i++) acc[i] = make_float4(0.f, 0.f, 0.f, 0.f);
        if (node < N_NODES) {
            int start = g_start[node];
            int end   = g_cursor[node];
            for (int e = start; e < end; e++) {
                int cn = g_bcol[e];
                const float4* xr = reinterpret_cast<const float4*>(x) + (size_t)cn * 16 + sub * 4;
                #pragma unroll
                for (int i = 0; i < 4; i++) {
                    float4 v = xr[i];
                    acc[i].x += v.x; acc[i].y += v.y; acc[i].z += v.z; acc[i].w += v.w;
                }
            }
            int d = end - start;
            float inv = 1.0f / (float)(d > 0 ? d : 1);
            #pragma unroll
            for (int i = 0; i < 4; i++) {
                acc[i].x *= inv; acc[i].y *= inv; acc[i].z *= inv; acc[i].w *= inv;
            }
        }

        // bf16 hi/lo split + swizzled store (x at cols 0..63, agg at 64..127)
        #pragma unroll
        for (int half = 0; half < 2; half++) {
            #pragma unroll
            for (int i = 0; i < 4; i++) {
                float4 v = half ? acc[i] : xv[i];
                __nv_bfloat16 h0 = __float2bfloat16_rn(v.x), h1 = __float2bfloat16_rn(v.y);
                __nv_bfloat16 h2 = __float2bfloat16_rn(v.z), h3 = __float2bfloat16_rn(v.w);
                float r0 = v.x - __bfloat162float(h0), r1 = v.y - __bfloat162float(h1);
                float r2 = v.z - __bfloat162float(h2), r3 = v.w - __bfloat162float(h3);
                int c = half * 64 + (sub * 4 + i) * 4;
                uint32_t off = phys(row, c);
                ull hv = (ull)bf2pack(__bfloat162float(h0), __bfloat162float(h1))
                       | ((ull)bf2pack(__bfloat162float(h2), __bfloat162float(h3)) << 32);
                ull lv = (ull)bf2pack(r0, r1) | ((ull)bf2pack(r2, r3) << 32);
                *reinterpret_cast<ull*>(smem + SM_A_HI + off) = hv;
                *reinterpret_cast<ull*>(smem + SM_A_LO + off) = lv;
            }
        }
        if (tid < 128) {
            bias_s[tid]       = b1[tid];
            bias_s[128 + tid] = b2[tid];
            bias_s[256 + tid] = b3[tid];
            bias_s[384 + tid] = (tid < 64) ? b4[tid] : 0.f;
        }
    }
    CP_WAIT0();
    __syncthreads();

    layer_body<128, false>(smem, sb, out, wid, lane, m0, bias_s,       65536, 4096, tid);
    layer_body<128, false>(smem, sb, out, wid, lane, m0, bias_s + 128, 131072, 4096, tid);
    layer_body<128, false>(smem, sb, out, wid, lane, m0, bias_s + 256, 196608, 2048, tid);
    layer_body<64,  true >(smem, sb, out, wid, lane, m0, bias_s + 384, 0, 0, tid);
}

// ---------------- launch ----------------------------------------------------
extern "C" void kernel_launch(void* const* d_in, const int* in_sizes, int n_in,
                              void* d_out, int out_size) {
    const float* x  = (const float*)d_in[0];
    const int*   ei = (const int*)  d_in[1];
    const float* W1 = (const float*)d_in[2];
    const float* b1 = (const float*)d_in[3];
    const float* W2 = (const float*)d_in[4];
    const float* b2 = (const float*)d_in[5];
    const float* W3 = (const float*)d_in[6];
    const float* b3 = (const float*)d_in[7];
    const float* W4 = (const float*)d_in[8];
    const float* b4 = (const float*)d_in[9];
    float* out = (float*)d_out;

    cudaFuncSetAttribute(fused_mlp, cudaFuncAttributeMaxDynamicSharedMemorySize, SM_TOTAL);

    // CSR build
    zero_deg<<<NB, 256>>>();
    hist_kernel<<<(N_EDGES + 255) / 256, 256>>>(ei);
    alloc_kernel<<<NB, 256>>>();
    bin_kernel<<<(N_EDGES + 255) / 256, 256>>>(ei);
    // weights + fused gather/MLP
    prep_weights<<<(57344 + 255) / 256, 256>>>(W1, W2, W3, W4);
    int gblocks = (N_NODES + 63) / 64;   // 1563
    fused_mlp<<<gblocks, 256, SM_TOTAL>>>(x, b1, b2, b3, b4, out);
}